// round 2
// baseline (speedup 1.0000x reference)
#include <cuda_runtime.h>

#define BATCH 32
#define TLEN  1024
#define HID   128
#define QT    128
#define KT    128
#define LDK   132
#define LDSIM 132
#define NTHREADS 256
#define LOG2E 1.4426950408889634f

// smem floats: q_s + k_t + sim_s + y_s + lam_s + lw_s
#define SMEM_FLOATS (QT*HID + HID*LDK + QT*LDSIM + 3*128)
#define SMEM_BYTES  (SMEM_FLOATS * 4)

__device__ __forceinline__ float ex2f(float x) {
    float y; asm("ex2.approx.ftz.f32 %0, %1;" : "=f"(y) : "f"(x)); return y;
}

__global__ __launch_bounds__(NTHREADS, 1)
void ema_kernel(const float* __restrict__ y,
                const int*   __restrict__ seq,
                const float* __restrict__ embd,
                const float* __restrict__ lam_w,
                const float* __restrict__ lam_b,
                float*       __restrict__ out)
{
    extern __shared__ float smem[];
    float* q_s   = smem;                    // [QT][HID]  normalized queries
    float* k_t   = q_s + QT * HID;          // [HID][LDK] normalized keys, transposed
    float* sim_s = k_t + HID * LDK;         // [QT][LDSIM]
    float* y_s   = sim_s + QT * LDSIM;      // [KT]
    float* lam_s = y_s + 128;               // [QT]
    float* lw_s  = lam_s + 128;             // [HID]

    const int tid  = threadIdx.x;
    const int lane = tid & 31;
    const int wid  = tid >> 5;

    // 128 CTAs: batch = blockIdx>>2, pair index p in [0,4). Tiles (p, 7-p): 9 units each.
    const int batch = blockIdx.x >> 2;
    const int pairp = blockIdx.x & 3;

    if (tid < HID) lw_s[tid] = lam_w[tid];
    const float lamb = lam_b[0];

    // GEMM thread mapping
    const int txl = tid & 15;
    const int tyl = tid >> 4;
    const int r0 = tyl * 8, c0 = txl * 8;

    const unsigned FULL = 0xffffffffu;

    for (int half = 0; half < 2; ++half) {
        const int qi = (half == 0) ? pairp : (7 - pairp);
        const int t0 = qi * QT;

        __syncthreads();   // lw_s ready (first iter); prior-tile readers done

        // ---- Q tile: gather, normalize, lambda ----
        for (int r = wid; r < QT; r += 8) {
            const int t = t0 + r;
            const int e = seq[batch * TLEN + t];
            const float* wrow = embd + (size_t)e * HID;
            float v0 = wrow[lane];
            float v1 = wrow[lane + 32];
            float v2 = wrow[lane + 64];
            float v3 = wrow[lane + 96];
            float ss = v0*v0 + v1*v1 + v2*v2 + v3*v3;
            float dl = v0*lw_s[lane] + v1*lw_s[lane+32] + v2*lw_s[lane+64] + v3*lw_s[lane+96];
            #pragma unroll
            for (int off = 16; off; off >>= 1) {
                ss += __shfl_xor_sync(FULL, ss, off);
                dl += __shfl_xor_sync(FULL, dl, off);
            }
            const float inv = rsqrtf(ss);
            q_s[r*HID + lane]      = v0 * inv;
            q_s[r*HID + lane + 32] = v1 * inv;
            q_s[r*HID + lane + 64] = v2 * inv;
            q_s[r*HID + lane + 96] = v3 * inv;
            if (lane == 0) lam_s[r] = __expf(dl + lamb);
        }
        __syncthreads();

        // ---- per-row state: warp wid owns rows [wid*16, wid*16+16) ----
        float carry[16], Sacc[16], Yacc[16], nl2[16];
        #pragma unroll
        for (int s = 0; s < 16; ++s) {
            carry[s] = 0.f; Sacc[s] = 0.f; Yacc[s] = 0.f;
            nl2[s] = -lam_s[wid*16 + s] * LOG2E;
        }

        // ---- key blocks, descending s ----
        for (int kb = qi; kb >= 0; --kb) {
            __syncthreads();   // previous scan done reading y_s / sim_s

            // K block: gather, normalize, transpose into k_t
            for (int c = wid; c < KT; c += 8) {
                const int s = kb * KT + c;
                const int e = seq[batch * TLEN + s];
                const float* wrow = embd + (size_t)e * HID;
                float v0 = wrow[lane];
                float v1 = wrow[lane + 32];
                float v2 = wrow[lane + 64];
                float v3 = wrow[lane + 96];
                float ss = v0*v0 + v1*v1 + v2*v2 + v3*v3;
                #pragma unroll
                for (int off = 16; off; off >>= 1)
                    ss += __shfl_xor_sync(FULL, ss, off);
                const float inv = rsqrtf(ss);
                k_t[(lane)      * LDK + c] = v0 * inv;
                k_t[(lane + 32) * LDK + c] = v1 * inv;
                k_t[(lane + 64) * LDK + c] = v2 * inv;
                k_t[(lane + 96) * LDK + c] = v3 * inv;
            }
            if (tid < 32)
                ((float4*)y_s)[tid] = ((const float4*)(y + batch * TLEN + kb * KT))[tid];
            __syncthreads();

            // ---- 128x128x128 fp32 GEMM, 8x8 per thread ----
            float acc[8][8];
            #pragma unroll
            for (int i = 0; i < 8; i++)
                #pragma unroll
                for (int j = 0; j < 8; j++) acc[i][j] = 0.f;

            #pragma unroll 1
            for (int h = 0; h < HID; h += 4) {
                float aa[8][4], bb[4][8];
                #pragma unroll
                for (int i = 0; i < 8; i++) {
                    float4 t4 = *(const float4*)&q_s[(r0 + i) * HID + h];
                    aa[i][0] = t4.x; aa[i][1] = t4.y; aa[i][2] = t4.z; aa[i][3] = t4.w;
                }
                #pragma unroll
                for (int hh = 0; hh < 4; hh++) {
                    float4 u  = *(const float4*)&k_t[(h + hh) * LDK + c0];
                    float4 w4 = *(const float4*)&k_t[(h + hh) * LDK + c0 + 4];
                    bb[hh][0] = u.x;  bb[hh][1] = u.y;  bb[hh][2] = u.z;  bb[hh][3] = u.w;
                    bb[hh][4] = w4.x; bb[hh][5] = w4.y; bb[hh][6] = w4.z; bb[hh][7] = w4.w;
                }
                #pragma unroll
                for (int hh = 0; hh < 4; hh++)
                    #pragma unroll
                    for (int i = 0; i < 8; i++)
                        #pragma unroll
                        for (int j = 0; j < 8; j++)
                            acc[i][j] = fmaf(aa[i][hh], bb[hh][j], acc[i][j]);
            }

            #pragma unroll
            for (int i = 0; i < 8; i++) {
                *(float4*)&sim_s[(r0 + i) * LDSIM + c0]     =
                    make_float4(acc[i][0], acc[i][1], acc[i][2], acc[i][3]);
                *(float4*)&sim_s[(r0 + i) * LDSIM + c0 + 4] =
                    make_float4(acc[i][4], acc[i][5], acc[i][6], acc[i][7]);
            }
            __syncthreads();

            // ---- warp-parallel suffix scan: lane handles cols [4*lane, 4*lane+4) ----
            const bool diag = (kb == qi);
            const int cbase = lane * 4;
            const float4 yv = ((const float4*)y_s)[lane];

            #pragma unroll
            for (int s = 0; s < 16; ++s) {
                const int r = wid * 16 + s;
                float4 sv = *(const float4*)&sim_s[r * LDSIM + cbase];
                float v0 = fmaf(sv.x, 0.5f, 0.5f);
                float v1 = fmaf(sv.y, 0.5f, 0.5f);
                float v2 = fmaf(sv.z, 0.5f, 0.5f);
                float v3 = fmaf(sv.w, 0.5f, 0.5f);
                if (diag) {
                    // strictly-causal: local col c valid iff c < r
                    v0 = (cbase + 0 < r) ? v0 : 0.f;
                    v1 = (cbase + 1 < r) ? v1 : 0.f;
                    v2 = (cbase + 2 < r) ? v2 : 0.f;
                    v3 = (cbase + 3 < r) ? v3 : 0.f;
                }
                // within-lane inclusive suffix (descending c)
                float t3 = v3;
                float t2 = t3 + v2;
                float t1 = t2 + v1;
                float tsum = t1 + v0;
                // cross-lane inclusive suffix scan of lane totals
                float S = tsum;
                #pragma unroll
                for (int off = 1; off < 32; off <<= 1) {
                    float n = __shfl_down_sync(FULL, S, off);
                    if (lane + off < 32) S += n;
                }
                const float base = carry[s] + (S - tsum);   // exclusive suffix + carry
                float w0 = v0 * ex2f(nl2[s] * (base + tsum));
                float w1 = v1 * ex2f(nl2[s] * (base + t1));
                float w2 = v2 * ex2f(nl2[s] * (base + t2));
                float w3 = v3 * ex2f(nl2[s] * (base + t3));
                Sacc[s] += (w0 + w1) + (w2 + w3);
                Yacc[s] += yv.x * w0 + yv.y * w1 + yv.z * w2 + yv.w * w3;
                carry[s] += __shfl_sync(FULL, S, 0);        // block total
            }
        }

        // ---- epilogue: reduce per-lane partials, write 16 rows per warp ----
        #pragma unroll
        for (int s = 0; s < 16; ++s) {
            float sv = Sacc[s], yv2 = Yacc[s];
            #pragma unroll
            for (int off = 16; off; off >>= 1) {
                sv  += __shfl_xor_sync(FULL, sv,  off);
                yv2 += __shfl_xor_sync(FULL, yv2, off);
            }
            if (lane == 0) {
                float o = yv2 / (sv + 1e-6f);
                o = fminf(fmaxf(o, 0.01f), 0.99f);
                out[batch * TLEN + t0 + wid * 16 + s] = o;
            }
        }
    }
}

extern "C" void kernel_launch(void* const* d_in, const int* in_sizes, int n_in,
                              void* d_out, int out_size)
{
    const float* y    = (const float*)d_in[0];
    const int*   seq  = (const int*)  d_in[1];
    const float* embd = (const float*)d_in[2];
    const float* lw   = (const float*)d_in[3];
    const float* lb   = (const float*)d_in[4];
    float* out = (float*)d_out;

    cudaFuncSetAttribute(ema_kernel,
                         cudaFuncAttributeMaxDynamicSharedMemorySize,
                         SMEM_BYTES);

    ema_kernel<<<BATCH * 4, NTHREADS, SMEM_BYTES>>>(y, seq, embd, lw, lb, out);
}

// round 3
// speedup vs baseline: 1.4166x; 1.4166x over previous
#include <cuda_runtime.h>
#include <cstdint>

#define BATCH 32
#define TLEN  1024
#define HID   128
#define QT    128
#define KT    128
#define LDQ   132
#define LDK   132
#define LDSIM 132
#define NTHREADS 256
#define LOG2E 1.4426950408889634f

// smem floats: q_s + k_t + sim_s + y_s + lw_s + nl2/carry/Sa/Ya
#define SMEM_FLOATS (QT*LDQ + HID*LDK + QT*LDSIM + 128 + 128 + 4*128)
#define SMEM_BYTES  (SMEM_FLOATS * 4)

__device__ __forceinline__ float ex2f(float x) {
    float y; asm("ex2.approx.ftz.f32 %0, %1;" : "=f"(y) : "f"(x)); return y;
}
__device__ __forceinline__ uint32_t f2tf32(float x) {
    uint32_t u; asm("cvt.rna.tf32.f32 %0, %1;" : "=r"(u) : "f"(x)); return u;
}
__device__ __forceinline__ void mma_tf32(float* c, const uint32_t* a,
                                         uint32_t b0, uint32_t b1) {
    asm volatile(
        "mma.sync.aligned.m16n8k8.row.col.f32.tf32.tf32.f32 "
        "{%0,%1,%2,%3}, {%4,%5,%6,%7}, {%8,%9}, {%0,%1,%2,%3};"
        : "+f"(c[0]), "+f"(c[1]), "+f"(c[2]), "+f"(c[3])
        : "r"(a[0]), "r"(a[1]), "r"(a[2]), "r"(a[3]), "r"(b0), "r"(b1));
}

__global__ __launch_bounds__(NTHREADS, 1)
void ema_kernel(const float* __restrict__ y,
                const int*   __restrict__ seq,
                const float* __restrict__ embd,
                const float* __restrict__ lam_w,
                const float* __restrict__ lam_b,
                float*       __restrict__ out)
{
    extern __shared__ float smem[];
    float*    q_s   = smem;                       // [QT][LDQ]  tf32 queries (as bits)
    float*    k_t   = q_s + QT * LDQ;             // [HID][LDK] tf32 keys, transposed
    float*    sim_s = k_t + HID * LDK;            // [QT][LDSIM]
    float*    y_s   = sim_s + QT * LDSIM;         // [KT]
    float*    lw_s  = y_s + 128;                  // [HID]
    float*    nl2_s = lw_s + 128;                 // [QT]
    float*    ca_s  = nl2_s + 128;                // carry
    float*    Sa_s  = ca_s + 128;
    float*    Ya_s  = Sa_s + 128;
    uint32_t* q_u   = (uint32_t*)q_s;
    uint32_t* k_u   = (uint32_t*)k_t;

    const int tid  = threadIdx.x;
    const int lane = tid & 31;
    const int wid  = tid >> 5;
    const unsigned FULL = 0xffffffffu;

    // 128 CTAs: tile pair (p, 7-p) per (batch, p) -> 9 key-block units each
    const int batch = blockIdx.x >> 2;
    const int pairp = blockIdx.x & 3;

    if (tid < HID) lw_s[tid] = lam_w[tid];
    const float lamb = lam_b[0];

    // GEMM warp mapping: 4x2 warps, each computes a 32x64 strip
    const int m0 = (wid >> 1) * 32;
    const int n0 = (wid & 1) * 64;
    const int g  = lane >> 2;        // group row
    const int tg = lane & 3;         // thread-in-group

    for (int half = 0; half < 2; ++half) {
        const int qi = (half == 0) ? pairp : (7 - pairp);
        const int t0 = qi * QT;

        __syncthreads();   // lw_s ready / previous epilogue readers done

        // ---- Q tile: gather, normalize, lambda; store tf32-rounded ----
        for (int r = wid; r < QT; r += 8) {
            const int t = t0 + r;
            const int e = seq[batch * TLEN + t];
            const float* wrow = embd + (size_t)e * HID;
            float v0 = wrow[lane];
            float v1 = wrow[lane + 32];
            float v2 = wrow[lane + 64];
            float v3 = wrow[lane + 96];
            float ss = v0*v0 + v1*v1 + v2*v2 + v3*v3;
            float dl = v0*lw_s[lane] + v1*lw_s[lane+32] + v2*lw_s[lane+64] + v3*lw_s[lane+96];
            #pragma unroll
            for (int off = 16; off; off >>= 1) {
                ss += __shfl_xor_sync(FULL, ss, off);
                dl += __shfl_xor_sync(FULL, dl, off);
            }
            const float inv = rsqrtf(ss);
            q_u[r*LDQ + lane]      = f2tf32(v0 * inv);
            q_u[r*LDQ + lane + 32] = f2tf32(v1 * inv);
            q_u[r*LDQ + lane + 64] = f2tf32(v2 * inv);
            q_u[r*LDQ + lane + 96] = f2tf32(v3 * inv);
            if (lane == 0) nl2_s[r] = -__expf(dl + lamb) * LOG2E;
        }
        if (tid < QT) { ca_s[tid] = 0.f; Sa_s[tid] = 0.f; Ya_s[tid] = 0.f; }
        __syncthreads();

        // ---- key blocks, descending s ----
        for (int kb = qi; kb >= 0; --kb) {
            __syncthreads();   // previous scan done with sim_s / y_s

            // K block: gather, normalize, transpose into k_t (tf32)
            for (int c = wid; c < KT; c += 8) {
                const int s = kb * KT + c;
                const int e = seq[batch * TLEN + s];
                const float* wrow = embd + (size_t)e * HID;
                float v0 = wrow[lane];
                float v1 = wrow[lane + 32];
                float v2 = wrow[lane + 64];
                float v3 = wrow[lane + 96];
                float ss = v0*v0 + v1*v1 + v2*v2 + v3*v3;
                #pragma unroll
                for (int off = 16; off; off >>= 1)
                    ss += __shfl_xor_sync(FULL, ss, off);
                const float inv = rsqrtf(ss);
                k_u[(lane)      * LDK + c] = f2tf32(v0 * inv);
                k_u[(lane + 32) * LDK + c] = f2tf32(v1 * inv);
                k_u[(lane + 64) * LDK + c] = f2tf32(v2 * inv);
                k_u[(lane + 96) * LDK + c] = f2tf32(v3 * inv);
            }
            if (tid < 32)
                ((float4*)y_s)[tid] = ((const float4*)(y + batch * TLEN + kb * KT))[tid];
            __syncthreads();

            // ---- 128x128x128 tf32 tensor GEMM: warp strip 32x64 ----
            float acc[2][8][4];
            #pragma unroll
            for (int mt = 0; mt < 2; mt++)
                #pragma unroll
                for (int nt = 0; nt < 8; nt++)
                    #pragma unroll
                    for (int j = 0; j < 4; j++) acc[mt][nt][j] = 0.f;

            #pragma unroll 4
            for (int ks = 0; ks < 16; ++ks) {
                const int k = ks * 8;
                uint32_t a[2][4];
                #pragma unroll
                for (int mt = 0; mt < 2; mt++) {
                    const int row = m0 + mt * 16 + g;
                    a[mt][0] = q_u[(row)     * LDQ + k + tg];
                    a[mt][1] = q_u[(row + 8) * LDQ + k + tg];
                    a[mt][2] = q_u[(row)     * LDQ + k + tg + 4];
                    a[mt][3] = q_u[(row + 8) * LDQ + k + tg + 4];
                }
                #pragma unroll
                for (int nt = 0; nt < 8; nt++) {
                    const int n = n0 + nt * 8 + g;
                    uint32_t b0 = k_u[(k + tg)     * LDK + n];
                    uint32_t b1 = k_u[(k + tg + 4) * LDK + n];
                    mma_tf32(acc[0][nt], a[0], b0, b1);
                    mma_tf32(acc[1][nt], a[1], b0, b1);
                }
            }

            // store sim tile (fragment layout -> row-major smem)
            #pragma unroll
            for (int mt = 0; mt < 2; mt++) {
                const int row = m0 + mt * 16 + g;
                #pragma unroll
                for (int nt = 0; nt < 8; nt++) {
                    const int col = n0 + nt * 8 + tg * 2;
                    *(float2*)&sim_s[(row)     * LDSIM + col] =
                        make_float2(acc[mt][nt][0], acc[mt][nt][1]);
                    *(float2*)&sim_s[(row + 8) * LDSIM + col] =
                        make_float2(acc[mt][nt][2], acc[mt][nt][3]);
                }
            }
            __syncthreads();

            // ---- warp-parallel suffix scan; warp owns rows [wid*16, +16) ----
            const bool diag = (kb == qi);
            const int cbase = lane * 4;
            const float4 yv = ((const float4*)y_s)[lane];

            #pragma unroll 2
            for (int s = 0; s < 16; ++s) {
                const int r = wid * 16 + s;
                const float nl2 = nl2_s[r];     // broadcast
                const float cy  = ca_s[r];      // broadcast
                float4 sv = *(const float4*)&sim_s[r * LDSIM + cbase];
                float v0 = fmaf(sv.x, 0.5f, 0.5f);
                float v1 = fmaf(sv.y, 0.5f, 0.5f);
                float v2 = fmaf(sv.z, 0.5f, 0.5f);
                float v3 = fmaf(sv.w, 0.5f, 0.5f);
                if (diag) {
                    v0 = (cbase + 0 < r) ? v0 : 0.f;
                    v1 = (cbase + 1 < r) ? v1 : 0.f;
                    v2 = (cbase + 2 < r) ? v2 : 0.f;
                    v3 = (cbase + 3 < r) ? v3 : 0.f;
                }
                // within-lane inclusive suffix (descending c)
                float t3 = v3;
                float t2 = t3 + v2;
                float t1 = t2 + v1;
                float tsum = t1 + v0;
                // cross-lane suffix scan of lane totals
                float S = tsum;
                #pragma unroll
                for (int off = 1; off < 32; off <<= 1) {
                    float n = __shfl_down_sync(FULL, S, off);
                    if (lane + off < 32) S += n;
                }
                const float base = cy + (S - tsum);
                float w0 = v0 * ex2f(nl2 * (base + tsum));
                float w1 = v1 * ex2f(nl2 * (base + t1));
                float w2 = v2 * ex2f(nl2 * (base + t2));
                float w3 = v3 * ex2f(nl2 * (base + t3));
                float sw = (w0 + w1) + (w2 + w3);
                float yw = yv.x * w0 + yv.y * w1 + yv.z * w2 + yv.w * w3;
                #pragma unroll
                for (int off = 16; off; off >>= 1) {
                    sw += __shfl_xor_sync(FULL, sw, off);
                    yw += __shfl_xor_sync(FULL, yw, off);
                }
                const float tot = __shfl_sync(FULL, S, 0);
                if (lane == 0) {
                    ca_s[r] = cy + tot;
                    Sa_s[r] += sw;
                    Ya_s[r] += yw;
                }
            }
        }
        __syncthreads();

        // ---- epilogue ----
        if (tid < QT) {
            float o = Ya_s[tid] / (Sa_s[tid] + 1e-6f);
            o = fminf(fmaxf(o, 0.01f), 0.99f);
            out[batch * TLEN + t0 + tid] = o;
        }
    }
}

extern "C" void kernel_launch(void* const* d_in, const int* in_sizes, int n_in,
                              void* d_out, int out_size)
{
    const float* y    = (const float*)d_in[0];
    const int*   seq  = (const int*)  d_in[1];
    const float* embd = (const float*)d_in[2];
    const float* lw   = (const float*)d_in[3];
    const float* lb   = (const float*)d_in[4];
    float* out = (float*)d_out;

    cudaFuncSetAttribute(ema_kernel,
                         cudaFuncAttributeMaxDynamicSharedMemorySize,
                         SMEM_BYTES);

    ema_kernel<<<BATCH * 4, NTHREADS, SMEM_BYTES>>>(y, seq, embd, lw, lb, out);
}

// round 4
// speedup vs baseline: 2.6483x; 1.8694x over previous
#include <cuda_runtime.h>
#include <cstdint>

#define BATCH 32
#define TLEN  1024
#define HID   128
#define QT    128
#define KT    128
#define LD    132
#define NTHREADS 256
#define LOG2E 1.4426950408889634f

// smem floats: q + k + sim + y2 + nl2 + ca + Sa + Ya
#define SMEM_FLOATS (3*QT*LD + 2*128 + 4*128)
#define SMEM_BYTES  (SMEM_FLOATS * 4)

__device__ float g_xn[(size_t)BATCH * TLEN * HID];   // tf32-rounded normalized embeddings
__device__ float g_nl2[BATCH * TLEN];                // -lambda * log2(e)

__device__ __forceinline__ float ex2f(float x) {
    float y; asm("ex2.approx.ftz.f32 %0, %1;" : "=f"(y) : "f"(x)); return y;
}
__device__ __forceinline__ uint32_t f2tf32(float x) {
    uint32_t u; asm("cvt.rna.tf32.f32 %0, %1;" : "=r"(u) : "f"(x)); return u;
}
__device__ __forceinline__ void mma_tf32(float* c, const uint32_t* a,
                                         uint32_t b0, uint32_t b1) {
    asm volatile(
        "mma.sync.aligned.m16n8k8.row.col.f32.tf32.tf32.f32 "
        "{%0,%1,%2,%3}, {%4,%5,%6,%7}, {%8,%9}, {%0,%1,%2,%3};"
        : "+f"(c[0]), "+f"(c[1]), "+f"(c[2]), "+f"(c[3])
        : "r"(a[0]), "r"(a[1]), "r"(a[2]), "r"(a[3]), "r"(b0), "r"(b1));
}
__device__ __forceinline__ void cp16(uint32_t dst, const void* src) {
    asm volatile("cp.async.ca.shared.global [%0], [%1], 16;" :: "r"(dst), "l"(src));
}
__device__ __forceinline__ void cp_wait_all() {
    asm volatile("cp.async.wait_all;" ::: "memory");
}

// ---- Pass 1: normalize every (b,t) token once, compute lambda once ----
__global__ __launch_bounds__(NTHREADS)
void prep_kernel(const int* __restrict__ seq,
                 const float* __restrict__ embd,
                 const float* __restrict__ lam_w,
                 const float* __restrict__ lam_b)
{
    const int lane = threadIdx.x & 31;
    const int wid  = threadIdx.x >> 5;
    const int row  = blockIdx.x * 8 + wid;          // global (b,t) index
    const unsigned FULL = 0xffffffffu;

    const int e = seq[row];
    const float* w = embd + (size_t)e * HID;
    float v0 = w[lane], v1 = w[lane+32], v2 = w[lane+64], v3 = w[lane+96];
    float l0 = lam_w[lane], l1 = lam_w[lane+32], l2 = lam_w[lane+64], l3 = lam_w[lane+96];
    float ss = v0*v0 + v1*v1 + v2*v2 + v3*v3;
    float dl = v0*l0 + v1*l1 + v2*l2 + v3*l3;
    #pragma unroll
    for (int off = 16; off; off >>= 1) {
        ss += __shfl_xor_sync(FULL, ss, off);
        dl += __shfl_xor_sync(FULL, dl, off);
    }
    const float inv = rsqrtf(ss);
    uint32_t* dst = (uint32_t*)(g_xn + (size_t)row * HID);
    dst[lane]      = f2tf32(v0 * inv);
    dst[lane + 32] = f2tf32(v1 * inv);
    dst[lane + 64] = f2tf32(v2 * inv);
    dst[lane + 96] = f2tf32(v3 * inv);
    if (lane == 0) g_nl2[row] = -__expf(dl + lam_b[0]) * LOG2E;
}

// ---- Pass 2: main kernel ----
__global__ __launch_bounds__(NTHREADS, 1)
void ema_kernel(const float* __restrict__ y, float* __restrict__ out)
{
    extern __shared__ float smem[];
    float*    q_s   = smem;                 // [QT][LD]  tf32 queries
    float*    k_s   = q_s + QT * LD;        // [KT][LD]  tf32 keys (row-major = col-major B)
    float*    sim_s = k_s + KT * LD;        // [QT][LD]
    float*    y2    = sim_s + QT * LD;      // [2][128]
    float*    nl2_s = y2 + 256;             // [128]
    float*    ca_s  = nl2_s + 128;
    float*    Sa_s  = ca_s + 128;
    float*    Ya_s  = Sa_s + 128;
    uint32_t* q_u   = (uint32_t*)q_s;
    uint32_t* k_u   = (uint32_t*)k_s;

    const uint32_t q_sa = (uint32_t)__cvta_generic_to_shared(q_s);
    const uint32_t k_sa = (uint32_t)__cvta_generic_to_shared(k_s);
    const uint32_t y_sa = (uint32_t)__cvta_generic_to_shared(y2);

    const int tid  = threadIdx.x;
    const int lane = tid & 31;
    const int wid  = tid >> 5;
    const unsigned FULL = 0xffffffffu;

    const int batch = blockIdx.x >> 2;
    const int pairp = blockIdx.x & 3;

    // GEMM warp mapping: 4x2 warps -> 32x64 strip each
    const int m0 = (wid >> 1) * 32;
    const int n0 = (wid & 1) * 64;
    const int g  = lane >> 2;
    const int tg = lane & 3;

    const float* xbase = g_xn + (size_t)batch * TLEN * HID;
    const float* ybase = y + batch * TLEN;

    for (int half = 0; half < 2; ++half) {
        const int qi = (half == 0) ? pairp : (7 - pairp);
        const int t0 = qi * QT;

        __syncthreads();   // previous half fully done with smem

        // prologue: async-copy Q tile, first K block, first y block
        {
            const float* qsrc = xbase + (size_t)t0 * HID;
            const float* ksrc = xbase + (size_t)qi * KT * HID;
            #pragma unroll
            for (int i = 0; i < 16; ++i) {
                const int c = tid + i * 256;         // 4096 chunks of 16B
                const int row = c >> 5, j = c & 31;
                cp16(q_sa + (row * LD + 4*j) * 4, qsrc + row * HID + 4*j);
                cp16(k_sa + (row * LD + 4*j) * 4, ksrc + row * HID + 4*j);
            }
            if (tid < 32) cp16(y_sa + tid * 16, ybase + qi * KT + tid * 4);
            if (tid < 128) {
                ca_s[tid] = 0.f; Sa_s[tid] = 0.f; Ya_s[tid] = 0.f;
                nl2_s[tid] = g_nl2[batch * TLEN + t0 + tid];
            }
        }
        cp_wait_all();
        __syncthreads();

        int buf = 0;
        for (int kb = qi; kb >= 0; --kb, buf ^= 1) {
            // ---- 128x128x128 tf32 tensor GEMM ----
            float acc[2][8][4];
            #pragma unroll
            for (int mt = 0; mt < 2; mt++)
                #pragma unroll
                for (int nt = 0; nt < 8; nt++)
                    #pragma unroll
                    for (int j = 0; j < 4; j++) acc[mt][nt][j] = 0.f;

            #pragma unroll 4
            for (int ks = 0; ks < 16; ++ks) {
                const int k = ks * 8;
                uint32_t a[2][4];
                #pragma unroll
                for (int mt = 0; mt < 2; mt++) {
                    const int row = m0 + mt * 16 + g;
                    a[mt][0] = q_u[(row)     * LD + k + tg];
                    a[mt][1] = q_u[(row + 8) * LD + k + tg];
                    a[mt][2] = q_u[(row)     * LD + k + tg + 4];
                    a[mt][3] = q_u[(row + 8) * LD + k + tg + 4];
                }
                #pragma unroll
                for (int nt = 0; nt < 8; nt++) {
                    const int n = n0 + nt * 8 + g;
                    uint32_t b0 = k_u[n * LD + k + tg];
                    uint32_t b1 = k_u[n * LD + k + tg + 4];
                    mma_tf32(acc[0][nt], a[0], b0, b1);
                    mma_tf32(acc[1][nt], a[1], b0, b1);
                }
            }

            // store sim tile
            #pragma unroll
            for (int mt = 0; mt < 2; mt++) {
                const int row = m0 + mt * 16 + g;
                #pragma unroll
                for (int nt = 0; nt < 8; nt++) {
                    const int col = n0 + nt * 8 + tg * 2;
                    *(float2*)&sim_s[(row)     * LD + col] =
                        make_float2(acc[mt][nt][0], acc[mt][nt][1]);
                    *(float2*)&sim_s[(row + 8) * LD + col] =
                        make_float2(acc[mt][nt][2], acc[mt][nt][3]);
                }
            }
            __syncthreads();   // sim ready; k_s free; y2[buf] stable

            // prefetch next K block + y into free buffers (overlaps scan)
            if (kb > 0) {
                const float* ksrc = xbase + (size_t)(kb - 1) * KT * HID;
                #pragma unroll
                for (int i = 0; i < 16; ++i) {
                    const int c = tid + i * 256;
                    const int row = c >> 5, j = c & 31;
                    cp16(k_sa + (row * LD + 4*j) * 4, ksrc + row * HID + 4*j);
                }
                if (tid < 32)
                    cp16(y_sa + (buf ^ 1) * 512 + tid * 16,
                         ybase + (kb - 1) * KT + tid * 4);
            }

            // ---- warp-parallel suffix scan; warp owns rows [wid*16, +16) ----
            const bool diag = (kb == qi);
            const int cbase = lane * 4;
            const float4 yv = ((const float4*)(y2 + buf * 128))[lane];

            #pragma unroll 2
            for (int s = 0; s < 16; ++s) {
                const int r = wid * 16 + s;
                const float nl2 = nl2_s[r];
                const float cy  = ca_s[r];
                float4 sv = *(const float4*)&sim_s[r * LD + cbase];
                float v0 = fmaf(sv.x, 0.5f, 0.5f);
                float v1 = fmaf(sv.y, 0.5f, 0.5f);
                float v2 = fmaf(sv.z, 0.5f, 0.5f);
                float v3 = fmaf(sv.w, 0.5f, 0.5f);
                if (diag) {
                    v0 = (cbase + 0 < r) ? v0 : 0.f;
                    v1 = (cbase + 1 < r) ? v1 : 0.f;
                    v2 = (cbase + 2 < r) ? v2 : 0.f;
                    v3 = (cbase + 3 < r) ? v3 : 0.f;
                }
                float t3 = v3;
                float t2 = t3 + v2;
                float t1 = t2 + v1;
                float tsum = t1 + v0;
                float S = tsum;
                #pragma unroll
                for (int off = 1; off < 32; off <<= 1) {
                    float n = __shfl_down_sync(FULL, S, off);
                    if (lane + off < 32) S += n;
                }
                const float base = cy + (S - tsum);
                float w0 = v0 * ex2f(nl2 * (base + tsum));
                float w1 = v1 * ex2f(nl2 * (base + t1));
                float w2 = v2 * ex2f(nl2 * (base + t2));
                float w3 = v3 * ex2f(nl2 * (base + t3));
                float sw = (w0 + w1) + (w2 + w3);
                float yw = yv.x * w0 + yv.y * w1 + yv.z * w2 + yv.w * w3;
                #pragma unroll
                for (int off = 16; off; off >>= 1) {
                    sw += __shfl_xor_sync(FULL, sw, off);
                    yw += __shfl_xor_sync(FULL, yw, off);
                }
                const float tot = __shfl_sync(FULL, S, 0);
                if (lane == 0) {
                    ca_s[r] = cy + tot;
                    Sa_s[r] += sw;
                    Ya_s[r] += yw;
                }
            }

            cp_wait_all();
            __syncthreads();   // prefetched K/y visible; scan done with sim
        }

        // epilogue
        if (tid < QT) {
            float o = Ya_s[tid] / (Sa_s[tid] + 1e-6f);
            o = fminf(fmaxf(o, 0.01f), 0.99f);
            out[batch * TLEN + t0 + tid] = o;
        }
    }
}

extern "C" void kernel_launch(void* const* d_in, const int* in_sizes, int n_in,
                              void* d_out, int out_size)
{
    const float* y    = (const float*)d_in[0];
    const int*   seq  = (const int*)  d_in[1];
    const float* embd = (const float*)d_in[2];
    const float* lw   = (const float*)d_in[3];
    const float* lb   = (const float*)d_in[4];
    float* out = (float*)d_out;

    cudaFuncSetAttribute(ema_kernel,
                         cudaFuncAttributeMaxDynamicSharedMemorySize,
                         SMEM_BYTES);

    prep_kernel<<<BATCH * TLEN / 8, NTHREADS>>>(seq, embd, lw, lb);
    ema_kernel<<<BATCH * 4, NTHREADS, SMEM_BYTES>>>(y, out);
}

// round 5
// speedup vs baseline: 3.1111x; 1.1747x over previous
#include <cuda_runtime.h>
#include <cstdint>

#define BATCH 32
#define TLEN  1024
#define HID   128
#define QT    128
#define KT    128
#define LD    132
#define NTHREADS 256
#define LOG2E 1.4426950408889634f

// smem floats: q + k + sim + y2 + nl2 + ca
#define SMEM_FLOATS (3*QT*LD + 2*128 + 2*128)
#define SMEM_BYTES  (SMEM_FLOATS * 4)

__device__ float g_xn[(size_t)BATCH * TLEN * HID];   // tf32-rounded normalized embeddings
__device__ float g_nl2[BATCH * TLEN];                // -lambda * log2(e)

__device__ __forceinline__ float ex2f(float x) {
    float y; asm("ex2.approx.ftz.f32 %0, %1;" : "=f"(y) : "f"(x)); return y;
}
__device__ __forceinline__ uint32_t f2tf32(float x) {
    uint32_t u; asm("cvt.rna.tf32.f32 %0, %1;" : "=r"(u) : "f"(x)); return u;
}
__device__ __forceinline__ void mma_tf32(float* c, const uint32_t* a,
                                         uint32_t b0, uint32_t b1) {
    asm volatile(
        "mma.sync.aligned.m16n8k8.row.col.f32.tf32.tf32.f32 "
        "{%0,%1,%2,%3}, {%4,%5,%6,%7}, {%8,%9}, {%0,%1,%2,%3};"
        : "+f"(c[0]), "+f"(c[1]), "+f"(c[2]), "+f"(c[3])
        : "r"(a[0]), "r"(a[1]), "r"(a[2]), "r"(a[3]), "r"(b0), "r"(b1));
}
__device__ __forceinline__ void cp16(uint32_t dst, const void* src) {
    asm volatile("cp.async.ca.shared.global [%0], [%1], 16;" :: "r"(dst), "l"(src));
}
__device__ __forceinline__ void cp_wait_all() {
    asm volatile("cp.async.wait_all;" ::: "memory");
}

// ---- Pass 1: normalize every (b,t) token once, compute lambda once ----
__global__ __launch_bounds__(NTHREADS)
void prep_kernel(const int* __restrict__ seq,
                 const float* __restrict__ embd,
                 const float* __restrict__ lam_w,
                 const float* __restrict__ lam_b)
{
    const int lane = threadIdx.x & 31;
    const int wid  = threadIdx.x >> 5;
    const int row  = blockIdx.x * 8 + wid;
    const unsigned FULL = 0xffffffffu;

    const int e = seq[row];
    const float* w = embd + (size_t)e * HID;
    float v0 = w[lane], v1 = w[lane+32], v2 = w[lane+64], v3 = w[lane+96];
    float l0 = lam_w[lane], l1 = lam_w[lane+32], l2 = lam_w[lane+64], l3 = lam_w[lane+96];
    float ss = v0*v0 + v1*v1 + v2*v2 + v3*v3;
    float dl = v0*l0 + v1*l1 + v2*l2 + v3*l3;
    #pragma unroll
    for (int off = 16; off; off >>= 1) {
        ss += __shfl_xor_sync(FULL, ss, off);
        dl += __shfl_xor_sync(FULL, dl, off);
    }
    const float inv = rsqrtf(ss);
    uint32_t* dst = (uint32_t*)(g_xn + (size_t)row * HID);
    dst[lane]      = f2tf32(v0 * inv);
    dst[lane + 32] = f2tf32(v1 * inv);
    dst[lane + 64] = f2tf32(v2 * inv);
    dst[lane + 96] = f2tf32(v3 * inv);
    if (lane == 0) g_nl2[row] = -__expf(dl + lam_b[0]) * LOG2E;
}

// ---- Pass 2: main kernel ----
__global__ __launch_bounds__(NTHREADS, 1)
void ema_kernel(const float* __restrict__ y, float* __restrict__ out)
{
    extern __shared__ float smem[];
    float*    q_s   = smem;                 // [QT][LD]
    float*    k_s   = q_s + QT * LD;        // [KT][LD]
    float*    sim_s = k_s + KT * LD;        // [QT][LD]
    float*    y2    = sim_s + QT * LD;      // [2][128]
    float*    nl2_s = y2 + 256;             // [128]
    float*    ca_s  = nl2_s + 128;          // [128] carry
    uint32_t* q_u   = (uint32_t*)q_s;
    uint32_t* k_u   = (uint32_t*)k_s;

    const uint32_t q_sa = (uint32_t)__cvta_generic_to_shared(q_s);
    const uint32_t k_sa = (uint32_t)__cvta_generic_to_shared(k_s);
    const uint32_t y_sa = (uint32_t)__cvta_generic_to_shared(y2);

    const int tid  = threadIdx.x;
    const int lane = tid & 31;
    const int wid  = tid >> 5;
    const unsigned FULL = 0xffffffffu;

    const int batch = blockIdx.x >> 2;
    const int pairp = blockIdx.x & 3;

    const int m0 = (wid >> 1) * 32;
    const int n0 = (wid & 1) * 64;
    const int g  = lane >> 2;
    const int tg = lane & 3;

    const float* xbase = g_xn + (size_t)batch * TLEN * HID;
    const float* ybase = y + batch * TLEN;

    for (int half = 0; half < 2; ++half) {
        const int qi = (half == 0) ? pairp : (7 - pairp);
        const int t0 = qi * QT;

        __syncthreads();

        // prologue: async-copy Q tile, first K block, first y block
        {
            const float* qsrc = xbase + (size_t)t0 * HID;
            const float* ksrc = xbase + (size_t)qi * KT * HID;
            #pragma unroll
            for (int i = 0; i < 16; ++i) {
                const int c = tid + i * 256;
                const int row = c >> 5, j = c & 31;
                cp16(q_sa + (row * LD + 4*j) * 4, qsrc + row * HID + 4*j);
                cp16(k_sa + (row * LD + 4*j) * 4, ksrc + row * HID + 4*j);
            }
            if (tid < 32) cp16(y_sa + tid * 16, ybase + qi * KT + tid * 4);
            if (tid < 128) {
                ca_s[tid] = 0.f;
                nl2_s[tid] = g_nl2[batch * TLEN + t0 + tid];
            }
        }
        cp_wait_all();
        __syncthreads();

        // per-(lane,row) partial accumulators, reduced once per tile
        float Sacc[16], Yacc[16];
        #pragma unroll
        for (int s = 0; s < 16; ++s) { Sacc[s] = 0.f; Yacc[s] = 0.f; }

        int buf = 0;
        for (int kb = qi; kb >= 0; --kb, buf ^= 1) {
            // ---- 128x128x128 tf32 tensor GEMM ----
            float acc[2][8][4];
            #pragma unroll
            for (int mt = 0; mt < 2; mt++)
                #pragma unroll
                for (int nt = 0; nt < 8; nt++)
                    #pragma unroll
                    for (int j = 0; j < 4; j++) acc[mt][nt][j] = 0.f;

            #pragma unroll 4
            for (int ks = 0; ks < 16; ++ks) {
                const int k = ks * 8;
                uint32_t a[2][4];
                #pragma unroll
                for (int mt = 0; mt < 2; mt++) {
                    const int row = m0 + mt * 16 + g;
                    a[mt][0] = q_u[(row)     * LD + k + tg];
                    a[mt][1] = q_u[(row + 8) * LD + k + tg];
                    a[mt][2] = q_u[(row)     * LD + k + tg + 4];
                    a[mt][3] = q_u[(row + 8) * LD + k + tg + 4];
                }
                #pragma unroll
                for (int nt = 0; nt < 8; nt++) {
                    const int n = n0 + nt * 8 + g;
                    uint32_t b0 = k_u[n * LD + k + tg];
                    uint32_t b1 = k_u[n * LD + k + tg + 4];
                    mma_tf32(acc[0][nt], a[0], b0, b1);
                    mma_tf32(acc[1][nt], a[1], b0, b1);
                }
            }

            #pragma unroll
            for (int mt = 0; mt < 2; mt++) {
                const int row = m0 + mt * 16 + g;
                #pragma unroll
                for (int nt = 0; nt < 8; nt++) {
                    const int col = n0 + nt * 8 + tg * 2;
                    *(float2*)&sim_s[(row)     * LD + col] =
                        make_float2(acc[mt][nt][0], acc[mt][nt][1]);
                    *(float2*)&sim_s[(row + 8) * LD + col] =
                        make_float2(acc[mt][nt][2], acc[mt][nt][3]);
                }
            }
            __syncthreads();   // sim ready; k_s free; y2[buf] stable

            // prefetch next K block + y (overlaps scan)
            if (kb > 0) {
                const float* ksrc = xbase + (size_t)(kb - 1) * KT * HID;
                #pragma unroll
                for (int i = 0; i < 16; ++i) {
                    const int c = tid + i * 256;
                    const int row = c >> 5, j = c & 31;
                    cp16(k_sa + (row * LD + 4*j) * 4, ksrc + row * HID + 4*j);
                }
                if (tid < 32)
                    cp16(y_sa + (buf ^ 1) * 512 + tid * 16,
                         ybase + (kb - 1) * KT + tid * 4);
            }

            // ---- warp-parallel suffix scan; warp owns rows [wid*16, +16) ----
            const bool diag = (kb == qi);
            const int cbase = lane * 4;
            const float4 yv = ((const float4*)(y2 + buf * 128))[lane];

            #pragma unroll
            for (int s = 0; s < 16; ++s) {
                const int r = wid * 16 + s;
                const float nl2 = nl2_s[r];
                const float cy  = ca_s[r];
                float4 sv = *(const float4*)&sim_s[r * LD + cbase];
                float v0 = fmaf(sv.x, 0.5f, 0.5f);
                float v1 = fmaf(sv.y, 0.5f, 0.5f);
                float v2 = fmaf(sv.z, 0.5f, 0.5f);
                float v3 = fmaf(sv.w, 0.5f, 0.5f);
                if (diag) {
                    v0 = (cbase + 0 < r) ? v0 : 0.f;
                    v1 = (cbase + 1 < r) ? v1 : 0.f;
                    v2 = (cbase + 2 < r) ? v2 : 0.f;
                    v3 = (cbase + 3 < r) ? v3 : 0.f;
                }
                float t3 = v3;
                float t2 = t3 + v2;
                float t1 = t2 + v1;
                float tsum = t1 + v0;
                float S = tsum;                 // inclusive suffix of lane totals
                #pragma unroll
                for (int off = 1; off < 32; off <<= 1) {
                    float n = __shfl_down_sync(FULL, S, off);
                    if (lane + off < 32) S += n;
                }
                const float base = cy + (S - tsum);
                float w0 = v0 * ex2f(nl2 * (base + tsum));
                float w1 = v1 * ex2f(nl2 * (base + t1));
                float w2 = v2 * ex2f(nl2 * (base + t2));
                float w3 = v3 * ex2f(nl2 * (base + t3));
                Sacc[s] += (w0 + w1) + (w2 + w3);
                Yacc[s] += yv.x * w0 + yv.y * w1 + yv.z * w2 + yv.w * w3;
                // lane 0's inclusive suffix IS the block total
                if (lane == 0) ca_s[r] = cy + S;
            }

            cp_wait_all();
            __syncthreads();
        }

        // ---- epilogue: one reduction per row per tile ----
        #pragma unroll
        for (int s = 0; s < 16; ++s) {
            float sw = Sacc[s], yw = Yacc[s];
            #pragma unroll
            for (int off = 16; off; off >>= 1) {
                sw += __shfl_xor_sync(FULL, sw, off);
                yw += __shfl_xor_sync(FULL, yw, off);
            }
            if (lane == 0) {
                float o = yw / (sw + 1e-6f);
                o = fminf(fmaxf(o, 0.01f), 0.99f);
                out[batch * TLEN + t0 + wid * 16 + s] = o;
            }
        }
    }
}

extern "C" void kernel_launch(void* const* d_in, const int* in_sizes, int n_in,
                              void* d_out, int out_size)
{
    const float* y    = (const float*)d_in[0];
    const int*   seq  = (const int*)  d_in[1];
    const float* embd = (const float*)d_in[2];
    const float* lw   = (const float*)d_in[3];
    const float* lb   = (const float*)d_in[4];
    float* out = (float*)d_out;

    cudaFuncSetAttribute(ema_kernel,
                         cudaFuncAttributeMaxDynamicSharedMemorySize,
                         SMEM_BYTES);

    prep_kernel<<<BATCH * TLEN / 8, NTHREADS>>>(seq, embd, lw, lb);
    ema_kernel<<<BATCH * 4, NTHREADS, SMEM_BYTES>>>(y, out);
}

// round 6
// speedup vs baseline: 3.3738x; 1.0844x over previous
#include <cuda_runtime.h>
#include <cstdint>

#define BATCH 32
#define TLEN  1024
#define HID   128
#define QT    128
#define KT    128
#define LD    136
#define NTHREADS 512
#define LOG2E 1.4426950408889634f

// smem floats: q + k + sim + y2 + nl2 + ca
#define SMEM_FLOATS (3*QT*LD + 2*128 + 2*128)
#define SMEM_BYTES  (SMEM_FLOATS * 4)

__device__ float g_xn[(size_t)BATCH * TLEN * HID];   // tf32, k-permuted within 8-groups
__device__ float g_nl2[BATCH * TLEN];                // -lambda * log2(e)

__device__ __forceinline__ float ex2f(float x) {
    float y; asm("ex2.approx.ftz.f32 %0, %1;" : "=f"(y) : "f"(x)); return y;
}
__device__ __forceinline__ uint32_t f2tf32(float x) {
    uint32_t u; asm("cvt.rna.tf32.f32 %0, %1;" : "=r"(u) : "f"(x)); return u;
}
__device__ __forceinline__ void mma_tf32(float* c, const uint32_t* a,
                                         uint32_t b0, uint32_t b1) {
    asm volatile(
        "mma.sync.aligned.m16n8k8.row.col.f32.tf32.tf32.f32 "
        "{%0,%1,%2,%3}, {%4,%5,%6,%7}, {%8,%9}, {%0,%1,%2,%3};"
        : "+f"(c[0]), "+f"(c[1]), "+f"(c[2]), "+f"(c[3])
        : "r"(a[0]), "r"(a[1]), "r"(a[2]), "r"(a[3]), "r"(b0), "r"(b1));
}
__device__ __forceinline__ void cp16(uint32_t dst, const void* src) {
    asm volatile("cp.async.ca.shared.global [%0], [%1], 16;" :: "r"(dst), "l"(src));
}
__device__ __forceinline__ void cp_wait_all() {
    asm volatile("cp.async.wait_all;" ::: "memory");
}

// ---- Pass 1: normalize each (b,t) token once; store k-permuted tf32 ----
__global__ __launch_bounds__(256)
void prep_kernel(const int* __restrict__ seq,
                 const float* __restrict__ embd,
                 const float* __restrict__ lam_w,
                 const float* __restrict__ lam_b)
{
    const int lane = threadIdx.x & 31;
    const int wid  = threadIdx.x >> 5;
    const int row  = blockIdx.x * 8 + wid;
    const unsigned FULL = 0xffffffffu;

    const int e = seq[row];
    const float* w = embd + (size_t)e * HID;
    float v0 = w[lane], v1 = w[lane+32], v2 = w[lane+64], v3 = w[lane+96];
    float l0 = lam_w[lane], l1 = lam_w[lane+32], l2 = lam_w[lane+64], l3 = lam_w[lane+96];
    float ss = v0*v0 + v1*v1 + v2*v2 + v3*v3;
    float dl = v0*l0 + v1*l1 + v2*l2 + v3*l3;
    #pragma unroll
    for (int off = 16; off; off >>= 1) {
        ss += __shfl_xor_sync(FULL, ss, off);
        dl += __shfl_xor_sync(FULL, dl, off);
    }
    const float inv = rsqrtf(ss);
    // permute within 8-col group: original offset o -> slot (o<4 ? 2o : 2(o-4)+1)
    const int o  = lane & 7;
    const int pc = (lane & ~7) | (((o & 3) << 1) | (o >> 2));
    uint32_t* dst = (uint32_t*)(g_xn + (size_t)row * HID);
    dst[pc]      = f2tf32(v0 * inv);
    dst[pc + 32] = f2tf32(v1 * inv);
    dst[pc + 64] = f2tf32(v2 * inv);
    dst[pc + 96] = f2tf32(v3 * inv);
    if (lane == 0) g_nl2[row] = -__expf(dl + lam_b[0]) * LOG2E;
}

// ---- Pass 2: main kernel ----
__global__ __launch_bounds__(NTHREADS, 1)
void ema_kernel(const float* __restrict__ y, float* __restrict__ out)
{
    extern __shared__ float smem[];
    float*    q_s   = smem;                 // [QT][LD]
    float*    k_s   = q_s + QT * LD;        // [KT][LD]
    float*    sim_s = k_s + KT * LD;        // [QT][LD]
    float*    y2    = sim_s + QT * LD;      // [2][128]
    float*    nl2_s = y2 + 256;             // [128]
    float*    ca_s  = nl2_s + 128;          // [128] carry

    const uint32_t q_sa = (uint32_t)__cvta_generic_to_shared(q_s);
    const uint32_t k_sa = (uint32_t)__cvta_generic_to_shared(k_s);
    const uint32_t y_sa = (uint32_t)__cvta_generic_to_shared(y2);

    const int tid  = threadIdx.x;
    const int lane = tid & 31;
    const int wid  = tid >> 5;
    const unsigned FULL = 0xffffffffu;

    const int batch = blockIdx.x >> 2;
    const int pairp = blockIdx.x & 3;

    // 16 warps: 8(M) x 2(N) grid of 16x64 warp tiles
    const int m0 = (wid >> 1) * 16;
    const int n0 = (wid & 1) * 64;
    const int g  = lane >> 2;
    const int tg = lane & 3;

    const float* xbase = g_xn + (size_t)batch * TLEN * HID;
    const float* ybase = y + batch * TLEN;

    for (int half = 0; half < 2; ++half) {
        const int qi = (half == 0) ? pairp : (7 - pairp);
        const int t0 = qi * QT;

        __syncthreads();

        // prologue: async-copy Q tile, first K block, first y block
        {
            const float* qsrc = xbase + (size_t)t0 * HID;
            const float* ksrc = xbase + (size_t)qi * KT * HID;
            #pragma unroll
            for (int i = 0; i < 8; ++i) {
                const int c = tid + i * 512;           // 4096 16B chunks each
                const int row = c >> 5, j = c & 31;
                cp16(q_sa + (row * LD + 4*j) * 4, qsrc + row * HID + 4*j);
                cp16(k_sa + (row * LD + 4*j) * 4, ksrc + row * HID + 4*j);
            }
            if (tid < 32) cp16(y_sa + tid * 16, ybase + qi * KT + tid * 4);
            if (tid < 128) {
                ca_s[tid] = 0.f;
                nl2_s[tid] = g_nl2[batch * TLEN + t0 + tid];
            }
        }
        cp_wait_all();
        __syncthreads();

        // per-(lane,row) partials, reduced once per tile (8 rows per warp)
        float Sacc[8], Yacc[8];
        #pragma unroll
        for (int s = 0; s < 8; ++s) { Sacc[s] = 0.f; Yacc[s] = 0.f; }

        int buf = 0;
        for (int kb = qi; kb >= 0; --kb, buf ^= 1) {
            // ---- 128x128x128 tf32 tensor GEMM; warp tile 16x64 ----
            float acc[8][4];
            #pragma unroll
            for (int nt = 0; nt < 8; nt++)
                #pragma unroll
                for (int j = 0; j < 4; j++) acc[nt][j] = 0.f;

            #pragma unroll 4
            for (int ks = 0; ks < 16; ++ks) {
                const int k = ks * 8;
                uint32_t a[4];
                {
                    const int row = m0 + g;
                    float2 f0 = *(const float2*)&q_s[(row)     * LD + k + 2*tg];
                    float2 f1 = *(const float2*)&q_s[(row + 8) * LD + k + 2*tg];
                    a[0] = __float_as_uint(f0.x); a[1] = __float_as_uint(f1.x);
                    a[2] = __float_as_uint(f0.y); a[3] = __float_as_uint(f1.y);
                }
                #pragma unroll
                for (int nt = 0; nt < 8; nt++) {
                    const int n = n0 + nt * 8 + g;
                    float2 fb = *(const float2*)&k_s[n * LD + k + 2*tg];
                    mma_tf32(acc[nt], a, __float_as_uint(fb.x), __float_as_uint(fb.y));
                }
            }

            // store sim tile (conflict-free with LD=136)
            {
                const int row = m0 + g;
                #pragma unroll
                for (int nt = 0; nt < 8; nt++) {
                    const int col = n0 + nt * 8 + tg * 2;
                    *(float2*)&sim_s[(row)     * LD + col] = make_float2(acc[nt][0], acc[nt][1]);
                    *(float2*)&sim_s[(row + 8) * LD + col] = make_float2(acc[nt][2], acc[nt][3]);
                }
            }
            __syncthreads();   // sim ready; k_s consumed; y2[buf] stable

            // prefetch next K block + y (overlaps scan)
            if (kb > 0) {
                const float* ksrc = xbase + (size_t)(kb - 1) * KT * HID;
                #pragma unroll
                for (int i = 0; i < 8; ++i) {
                    const int c = tid + i * 512;
                    const int row = c >> 5, j = c & 31;
                    cp16(k_sa + (row * LD + 4*j) * 4, ksrc + row * HID + 4*j);
                }
                if (tid < 32)
                    cp16(y_sa + (buf ^ 1) * 512 + tid * 16,
                         ybase + (kb - 1) * KT + tid * 4);
            }

            // ---- warp-parallel suffix scan; warp owns rows [wid*8, +8) ----
            const bool diag = (kb == qi);
            const int cbase = lane * 4;
            const float4 yv = ((const float4*)(y2 + buf * 128))[lane];

            #pragma unroll
            for (int s = 0; s < 8; ++s) {
                const int r = wid * 8 + s;
                const float nl2 = nl2_s[r];
                const float cy  = ca_s[r];
                float4 sv = *(const float4*)&sim_s[r * LD + cbase];
                float v0 = fmaf(sv.x, 0.5f, 0.5f);
                float v1 = fmaf(sv.y, 0.5f, 0.5f);
                float v2 = fmaf(sv.z, 0.5f, 0.5f);
                float v3 = fmaf(sv.w, 0.5f, 0.5f);
                if (diag) {
                    v0 = (cbase + 0 < r) ? v0 : 0.f;
                    v1 = (cbase + 1 < r) ? v1 : 0.f;
                    v2 = (cbase + 2 < r) ? v2 : 0.f;
                    v3 = (cbase + 3 < r) ? v3 : 0.f;
                }
                float t3 = v3;
                float t2 = t3 + v2;
                float t1 = t2 + v1;
                float tsum = t1 + v0;
                float S = tsum;                 // inclusive suffix of lane totals
                #pragma unroll
                for (int off = 1; off < 32; off <<= 1) {
                    float n = __shfl_down_sync(FULL, S, off);
                    if (lane + off < 32) S += n;
                }
                const float base = cy + (S - tsum);
                float w0 = v0 * ex2f(nl2 * (base + tsum));
                float w1 = v1 * ex2f(nl2 * (base + t1));
                float w2 = v2 * ex2f(nl2 * (base + t2));
                float w3 = v3 * ex2f(nl2 * (base + t3));
                Sacc[s] += (w0 + w1) + (w2 + w3);
                Yacc[s] += yv.x * w0 + yv.y * w1 + yv.z * w2 + yv.w * w3;
                if (lane == 0) ca_s[r] = cy + S;   // block total
            }

            cp_wait_all();
            __syncthreads();
        }

        // ---- epilogue: one reduction per row per tile ----
        #pragma unroll
        for (int s = 0; s < 8; ++s) {
            float sw = Sacc[s], yw = Yacc[s];
            #pragma unroll
            for (int off = 16; off; off >>= 1) {
                sw += __shfl_xor_sync(FULL, sw, off);
                yw += __shfl_xor_sync(FULL, yw, off);
            }
            if (lane == 0) {
                float o = yw / (sw + 1e-6f);
                o = fminf(fmaxf(o, 0.01f), 0.99f);
                out[batch * TLEN + t0 + wid * 8 + s] = o;
            }
        }
    }
}

extern "C" void kernel_launch(void* const* d_in, const int* in_sizes, int n_in,
                              void* d_out, int out_size)
{
    const float* y    = (const float*)d_in[0];
    const int*   seq  = (const int*)  d_in[1];
    const float* embd = (const float*)d_in[2];
    const float* lw   = (const float*)d_in[3];
    const float* lb   = (const float*)d_in[4];
    float* out = (float*)d_out;

    cudaFuncSetAttribute(ema_kernel,
                         cudaFuncAttributeMaxDynamicSharedMemorySize,
                         SMEM_BYTES);

    prep_kernel<<<BATCH * TLEN / 8, 256>>>(seq, embd, lw, lb);
    ema_kernel<<<BATCH * 4, NTHREADS, SMEM_BYTES>>>(y, out);
}

// round 8
// speedup vs baseline: 3.4870x; 1.0335x over previous
#include <cuda_runtime.h>
#include <cstdint>

#define BATCH 32
#define TLEN  1024
#define HID   128
#define LD    136
#define NT    512
#define LOG2E 1.4426950408889634f

#define TILE_F (128*LD)
#define SM_Q   0
#define SM_K0  (TILE_F)
#define SM_K1  (2*TILE_F)
#define SM_Y   (3*TILE_F)          // 2*128 floats
#define SM_CA  (SM_Y + 256)        // 128 floats
#define SM_TOT (SM_CA + 128)       // 1024 floats (S / Y halves in epilogue)
#define SMEM_FLOATS (SM_TOT + 1024)
#define SMEM_BYTES  (SMEM_FLOATS * 4)

__device__ float g_xn[(size_t)BATCH * TLEN * HID];   // tf32, k-permuted within 8-groups
__device__ float g_nl2[BATCH * TLEN];                // -lambda * log2(e)

__device__ __forceinline__ float ex2f(float x) {
    float y; asm("ex2.approx.ftz.f32 %0, %1;" : "=f"(y) : "f"(x)); return y;
}
__device__ __forceinline__ uint32_t f2tf32(float x) {
    uint32_t u; asm("cvt.rna.tf32.f32 %0, %1;" : "=r"(u) : "f"(x)); return u;
}
__device__ __forceinline__ void mma_tf32(float* c, const uint32_t* a,
                                         uint32_t b0, uint32_t b1) {
    asm volatile(
        "mma.sync.aligned.m16n8k8.row.col.f32.tf32.tf32.f32 "
        "{%0,%1,%2,%3}, {%4,%5,%6,%7}, {%8,%9}, {%0,%1,%2,%3};"
        : "+f"(c[0]), "+f"(c[1]), "+f"(c[2]), "+f"(c[3])
        : "r"(a[0]), "r"(a[1]), "r"(a[2]), "r"(a[3]), "r"(b0), "r"(b1));
}
__device__ __forceinline__ void cp16(uint32_t dst, const void* src) {
    asm volatile("cp.async.ca.shared.global [%0], [%1], 16;" :: "r"(dst), "l"(src));
}
__device__ __forceinline__ void cp_wait_all() {
    asm volatile("cp.async.wait_all;" ::: "memory");
}

// ---- Pass 1: normalize each (b,t) token once; store k-permuted tf32 ----
__global__ __launch_bounds__(256)
void prep_kernel(const int* __restrict__ seq,
                 const float* __restrict__ embd,
                 const float* __restrict__ lam_w,
                 const float* __restrict__ lam_b)
{
    const int lane = threadIdx.x & 31;
    const int wid  = threadIdx.x >> 5;
    const int row  = blockIdx.x * 8 + wid;
    const unsigned FULL = 0xffffffffu;

    const int e = seq[row];
    const float* w = embd + (size_t)e * HID;
    float v0 = w[lane], v1 = w[lane+32], v2 = w[lane+64], v3 = w[lane+96];
    float l0 = lam_w[lane], l1 = lam_w[lane+32], l2 = lam_w[lane+64], l3 = lam_w[lane+96];
    float ss = v0*v0 + v1*v1 + v2*v2 + v3*v3;
    float dl = v0*l0 + v1*l1 + v2*l2 + v3*l3;
    #pragma unroll
    for (int off = 16; off; off >>= 1) {
        ss += __shfl_xor_sync(FULL, ss, off);
        dl += __shfl_xor_sync(FULL, dl, off);
    }
    const float inv = rsqrtf(ss);
    // permute within 8-col group: offset o -> (o<4 ? 2o : 2(o-4)+1)
    const int o  = lane & 7;
    const int pc = (lane & ~7) | (((o & 3) << 1) | (o >> 2));
    uint32_t* dst = (uint32_t*)(g_xn + (size_t)row * HID);
    dst[pc]      = f2tf32(v0 * inv);
    dst[pc + 32] = f2tf32(v1 * inv);
    dst[pc + 64] = f2tf32(v2 * inv);
    dst[pc + 96] = f2tf32(v3 * inv);
    if (lane == 0) g_nl2[row] = -__expf(dl + lam_b[0]) * LOG2E;
}

// ---- Pass 2: main kernel ----
__global__ __launch_bounds__(NT, 1)
void ema_kernel(const float* __restrict__ y, float* __restrict__ out)
{
    extern __shared__ float smem[];
    float* q_s   = smem + SM_Q;
    float* ks0   = smem + SM_K0;
    float* ks1   = smem + SM_K1;
    float* y2    = smem + SM_Y;
    float* ca_s  = smem + SM_CA;
    float* tot   = smem + SM_TOT;

    const uint32_t q_sa = (uint32_t)__cvta_generic_to_shared(q_s);
    const uint32_t k_sa[2] = { (uint32_t)__cvta_generic_to_shared(ks0),
                               (uint32_t)__cvta_generic_to_shared(ks1) };
    const uint32_t y_sa = (uint32_t)__cvta_generic_to_shared(y2);

    const int tid  = threadIdx.x;
    const int lane = tid & 31;
    const int wid  = tid >> 5;
    const unsigned FULL = 0xffffffffu;

    const int g  = lane >> 2;
    const int tg = lane & 3;
    const int mrow0 = (wid >> 2) * 32;    // 4x4 warp grid
    const int cw    = wid & 3;
    const int cb    = cw * 32;

    const int batch = blockIdx.x >> 2;
    const int pairp = blockIdx.x & 3;

    const float* xbase = g_xn + (size_t)batch * TLEN * HID;
    const float* ybase = y + batch * TLEN;

    // rows owned by this lane: mrow0 + 8*i + g
    int rown[4];
    #pragma unroll
    for (int i = 0; i < 4; ++i) rown[i] = mrow0 + 8 * i + g;

    for (int half = 0; half < 2; ++half) {
        const int qi = (half == 0) ? pairp : (7 - pairp);
        const int t0 = qi * 128;

        __syncthreads();    // previous half done with all smem

        // prologue: Q tile + y(qi)
        {
            const float* qsrc = xbase + (size_t)t0 * HID;
            #pragma unroll
            for (int i = 0; i < 8; ++i) {
                const int c = tid + i * 512;          // 4096 16B chunks
                const int r = c >> 5, j = c & 31;
                cp16(q_sa + (r * LD + 4 * j) * 4, qsrc + r * HID + 4 * j);
            }
            if (tid < 32) cp16(y_sa + tid * 16, ybase + qi * 128 + tid * 4);
            if (tid < 128) ca_s[tid] = 0.f;
        }
        float nl2r[4];
        #pragma unroll
        for (int i = 0; i < 4; ++i)
            nl2r[i] = g_nl2[batch * TLEN + t0 + rown[i]];
        cp_wait_all();
        __syncthreads();

        float Sacc[4] = {0.f, 0.f, 0.f, 0.f};
        float Yacc[4] = {0.f, 0.f, 0.f, 0.f};

        for (int it = 0; it <= qi; ++it) {
            const int kb = qi - it;

            // prefetch K(kb-1) -> k[it&1], y(kb-1) -> y2[(it+1)&1]  (overlaps GEMM+scan)
            if (kb > 0) {
                const float* ksrc = xbase + (size_t)(kb - 1) * 128 * HID;
                const uint32_t dst = k_sa[it & 1];
                #pragma unroll
                for (int i = 0; i < 8; ++i) {
                    const int c = tid + i * 512;
                    const int r = c >> 5, j = c & 31;
                    cp16(dst + (r * LD + 4 * j) * 4, ksrc + r * HID + 4 * j);
                }
                if (tid < 32)
                    cp16(y_sa + ((it + 1) & 1) * 512 + tid * 16,
                         ybase + (kb - 1) * 128 + tid * 4);
            }

            // ---- GEMM: warp tile 32x32; B = Q for diagonal block ----
            const float* bsrc = (it == 0) ? q_s : ((it & 1) ? ks0 : ks1);
            float acc[2][4][4];
            #pragma unroll
            for (int mt = 0; mt < 2; mt++)
                #pragma unroll
                for (int nt = 0; nt < 4; nt++)
                    #pragma unroll
                    for (int j = 0; j < 4; j++) acc[mt][nt][j] = 0.f;

            #pragma unroll 4
            for (int ks = 0; ks < 16; ++ks) {
                const int k = ks * 8;
                uint32_t a[2][4];
                #pragma unroll
                for (int mt = 0; mt < 2; mt++) {
                    const int r = mrow0 + mt * 16 + g;
                    float2 f0 = *(const float2*)&q_s[(r)     * LD + k + 2 * tg];
                    float2 f1 = *(const float2*)&q_s[(r + 8) * LD + k + 2 * tg];
                    a[mt][0] = __float_as_uint(f0.x); a[mt][1] = __float_as_uint(f1.x);
                    a[mt][2] = __float_as_uint(f0.y); a[mt][3] = __float_as_uint(f1.y);
                }
                #pragma unroll
                for (int nt = 0; nt < 4; nt++) {
                    const int n = cb + nt * 8 + g;
                    float2 fb = *(const float2*)&bsrc[n * LD + k + 2 * tg];
                    mma_tf32(acc[0][nt], a[0], __float_as_uint(fb.x), __float_as_uint(fb.y));
                    mma_tf32(acc[1][nt], a[1], __float_as_uint(fb.x), __float_as_uint(fb.y));
                }
            }

            // ---- scan from fragments ----
            const bool diag = (it == 0);
            const int col0 = cb + 2 * tg;

            // mask + (x+1)/2, in place
            #pragma unroll
            for (int i = 0; i < 4; ++i) {
                const int mt = i >> 1, c0i = (i & 1) * 2;
                #pragma unroll
                for (int nt = 0; nt < 4; nt++) {
                    float va = fmaf(acc[mt][nt][c0i],     0.5f, 0.5f);
                    float vb = fmaf(acc[mt][nt][c0i + 1], 0.5f, 0.5f);
                    if (diag) {
                        va = (col0 + nt * 8     < rown[i]) ? va : 0.f;
                        vb = (col0 + nt * 8 + 1 < rown[i]) ? vb : 0.f;
                    }
                    acc[mt][nt][c0i]     = va;
                    acc[mt][nt][c0i + 1] = vb;
                }
            }

            // per (row,frag): suffix over the 4 lanes of the group
            float sarr[4][4], ft[4][4];
            #pragma unroll
            for (int i = 0; i < 4; ++i) {
                const int mt = i >> 1, c0i = (i & 1) * 2;
                #pragma unroll
                for (int nt = 0; nt < 4; nt++) {
                    float s = acc[mt][nt][c0i] + acc[mt][nt][c0i + 1];
                    float u = __shfl_down_sync(FULL, s, 1);
                    s += (tg < 3) ? u : 0.f;
                    u = __shfl_down_sync(FULL, s, 2);
                    s += (tg < 2) ? u : 0.f;
                    sarr[i][nt] = s;
                    ft[i][nt] = __shfl_sync(FULL, s, lane & ~3);  // frag total
                }
            }

            // chunk totals -> smem
            if (tg == 0) {
                #pragma unroll
                for (int i = 0; i < 4; ++i)
                    tot[cw * 128 + rown[i]] =
                        ft[i][0] + ft[i][1] + ft[i][2] + ft[i][3];
            }
            __syncthreads();

            // y pairs for this block
            const int ybuf = it & 1;
            float2 yp[4];
            #pragma unroll
            for (int nt = 0; nt < 4; nt++)
                yp[nt] = *(const float2*)&y2[ybuf * 128 + cb + nt * 8 + 2 * tg];

            float pend[4];
            #pragma unroll
            for (int i = 0; i < 4; ++i) {
                const int r = rown[i];
                const float cy = ca_s[r];
                const float c0t = tot[r], c1t = tot[128 + r],
                            c2t = tot[256 + r], c3t = tot[384 + r];
                float base = cy;
                if (cw == 0)      base += c1t + c2t + c3t;
                else if (cw == 1) base += c2t + c3t;
                else if (cw == 2) base += c3t;
                pend[i] = cy + c0t + c1t + c2t + c3t;

                const int mt = i >> 1, c0i = (i & 1) * 2;
                float fsuf = 0.f;
                #pragma unroll
                for (int nt = 3; nt >= 0; --nt) {
                    const float va = acc[mt][nt][c0i];
                    const float vb = acc[mt][nt][c0i + 1];
                    const float sa = base + fsuf + sarr[i][nt];
                    const float wa = va * ex2f(nl2r[i] * sa);
                    const float wb = vb * ex2f(nl2r[i] * (sa - va));
                    Sacc[i] += wa + wb;
                    Yacc[i] += yp[nt].x * wa + yp[nt].y * wb;
                    fsuf += ft[i][nt];
                }
            }

            cp_wait_all();
            __syncthreads();    // tot reads done; prefetched K/y visible

            if (cw == 0 && tg == 0) {
                #pragma unroll
                for (int i = 0; i < 4; ++i) ca_s[rown[i]] = pend[i];
            }
        }

        // ---- epilogue ----
        #pragma unroll
        for (int i = 0; i < 4; ++i) {
            float s = Sacc[i], yv = Yacc[i];
            s  += __shfl_xor_sync(FULL, s, 1);  s  += __shfl_xor_sync(FULL, s, 2);
            yv += __shfl_xor_sync(FULL, yv, 1); yv += __shfl_xor_sync(FULL, yv, 2);
            if (tg == 0) {
                tot[cw * 128 + rown[i]]       = s;
                tot[512 + cw * 128 + rown[i]] = yv;
            }
        }
        __syncthreads();
        if (cw == 0) {
            #pragma unroll
            for (int i = 0; i < 4; ++i) {
                const int r = rown[i];
                float S = tot[r] + tot[128 + r] + tot[256 + r] + tot[384 + r];
                float Y = tot[512 + r] + tot[640 + r] + tot[768 + r] + tot[896 + r];
                float o = Y / (S + 1e-6f);
                o = fminf(fmaxf(o, 0.01f), 0.99f);
                out[batch * TLEN + t0 + r] = o;
            }
        }
    }
}

extern "C" void kernel_launch(void* const* d_in, const int* in_sizes, int n_in,
                              void* d_out, int out_size)
{
    const float* y    = (const float*)d_in[0];
    const int*   seq  = (const int*)  d_in[1];
    const float* embd = (const float*)d_in[2];
    const float* lw   = (const float*)d_in[3];
    const float* lb   = (const float*)d_in[4];
    float* out = (float*)d_out;

    cudaFuncSetAttribute(ema_kernel,
                         cudaFuncAttributeMaxDynamicSharedMemorySize, SMEM_BYTES);

    prep_kernel<<<BATCH * TLEN / 8, 256>>>(seq, embd, lw, lb);
    ema_kernel<<<BATCH * 4, NT, SMEM_BYTES>>>(y, out);
}

// round 9
// speedup vs baseline: 5.0284x; 1.4421x over previous
#include <cuda_runtime.h>
#include <cuda_fp16.h>
#include <cstdint>

#define BATCH 32
#define TLEN  1024
#define HID   128
#define LD_H  144              // halves per padded smem row (288 B)
#define NT    512
#define LOG2E 1.4426950408889634f

#define TILE_B (128 * LD_H * 2)        // 36864 B
#define SM_Q   0
#define SM_K0  TILE_B
#define SM_K1  (2 * TILE_B)
#define SM_Y   (3 * TILE_B)            // 2*128 floats (1024 B)
#define SM_CA  (SM_Y + 1024)           // 128 floats
#define SM_TOT (SM_CA + 512)           // 1024 floats
#define SMEM_BYTES (SM_TOT + 4096)

__device__ __half g_xn[(size_t)BATCH * TLEN * HID];  // fp16, k-permuted per 16-group
__device__ float  g_nl2[BATCH * TLEN];               // -lambda * log2(e)

__device__ __forceinline__ float ex2f(float x) {
    float y; asm("ex2.approx.ftz.f32 %0, %1;" : "=f"(y) : "f"(x)); return y;
}
__device__ __forceinline__ void mma_f16(float* c, uint32_t a0, uint32_t a1,
                                        uint32_t a2, uint32_t a3,
                                        uint32_t b0, uint32_t b1) {
    asm volatile(
        "mma.sync.aligned.m16n8k16.row.col.f32.f16.f16.f32 "
        "{%0,%1,%2,%3}, {%4,%5,%6,%7}, {%8,%9}, {%0,%1,%2,%3};"
        : "+f"(c[0]), "+f"(c[1]), "+f"(c[2]), "+f"(c[3])
        : "r"(a0), "r"(a1), "r"(a2), "r"(a3), "r"(b0), "r"(b1));
}
__device__ __forceinline__ void cp16(uint32_t dst, const void* src) {
    asm volatile("cp.async.ca.shared.global [%0], [%1], 16;" :: "r"(dst), "l"(src));
}
__device__ __forceinline__ void cp_wait_all() {
    asm volatile("cp.async.wait_all;" ::: "memory");
}

// ---- Pass 1: normalize each token once; store fp16 k-permuted ----
__global__ __launch_bounds__(256)
void prep_kernel(const int* __restrict__ seq,
                 const float* __restrict__ embd,
                 const float* __restrict__ lam_w,
                 const float* __restrict__ lam_b)
{
    const int lane = threadIdx.x & 31;
    const int wid  = threadIdx.x >> 5;
    const int row  = blockIdx.x * 8 + wid;
    const unsigned FULL = 0xffffffffu;

    const int e = seq[row];
    const float* w = embd + (size_t)e * HID;
    float v[4] = { w[lane], w[lane+32], w[lane+64], w[lane+96] };
    float ss = v[0]*v[0] + v[1]*v[1] + v[2]*v[2] + v[3]*v[3];
    float dl = v[0]*lam_w[lane] + v[1]*lam_w[lane+32]
             + v[2]*lam_w[lane+64] + v[3]*lam_w[lane+96];
    #pragma unroll
    for (int off = 16; off; off >>= 1) {
        ss += __shfl_xor_sync(FULL, ss, off);
        dl += __shfl_xor_sync(FULL, dl, off);
    }
    const float inv = rsqrtf(ss);
    __half* dst = g_xn + (size_t)row * HID;
    #pragma unroll
    for (int q = 0; q < 4; ++q) {
        const int c = lane + 32 * q;
        const int gk = c >> 4, u = (c >> 1) & 7, par = c & 1;
        const int slot = (u < 4) ? 2 * u : 2 * (u - 4) + 1;   // half2-unit permute
        dst[gk * 16 + slot * 2 + par] = __float2half_rn(v[q] * inv);
    }
    if (lane == 0) g_nl2[row] = -__expf(dl + lam_b[0]) * LOG2E;
}

// ---- GEMM + scan for one 128x128 key block ----
template<bool DIAG>
__device__ __forceinline__ void process_block(
    const __half* q_h, const __half* b_h, const float* yblk,
    float* tot, const float* ca_s,
    const float* nl2r, const int* rown, float* Sacc, float* Yacc, float* pend,
    int mrow0, int cb, int cw, int g, int tg)
{
    const unsigned FULL = 0xffffffffu;

    float acc[2][4][4];
    #pragma unroll
    for (int mt = 0; mt < 2; mt++)
        #pragma unroll
        for (int nt = 0; nt < 4; nt++)
            #pragma unroll
            for (int j = 0; j < 4; j++) acc[mt][nt][j] = 0.f;

    #pragma unroll
    for (int ks = 0; ks < 8; ++ks) {
        const int boff = ks * 16 + 4 * tg;   // halves
        uint2 a[2][2];
        #pragma unroll
        for (int mt = 0; mt < 2; ++mt) {
            const int r = mrow0 + mt * 16 + g;
            a[mt][0] = *(const uint2*)&q_h[r * LD_H + boff];
            a[mt][1] = *(const uint2*)&q_h[(r + 8) * LD_H + boff];
        }
        #pragma unroll
        for (int nt = 0; nt < 4; ++nt) {
            const int n = cb + nt * 8 + g;
            uint2 b = *(const uint2*)&b_h[n * LD_H + boff];
            mma_f16(acc[0][nt], a[0][0].x, a[0][1].x, a[0][0].y, a[0][1].y, b.x, b.y);
            mma_f16(acc[1][nt], a[1][0].x, a[1][1].x, a[1][0].y, a[1][1].y, b.x, b.y);
        }
    }

    // mask + (x+1)/2
    const int col0 = cb + 2 * tg;
    #pragma unroll
    for (int i = 0; i < 4; ++i) {
        const int mt = i >> 1, c0i = (i & 1) * 2;
        #pragma unroll
        for (int nt = 0; nt < 4; nt++) {
            float va = fmaf(acc[mt][nt][c0i],     0.5f, 0.5f);
            float vb = fmaf(acc[mt][nt][c0i + 1], 0.5f, 0.5f);
            if (DIAG) {
                va = (col0 + nt * 8     < rown[i]) ? va : 0.f;
                vb = (col0 + nt * 8 + 1 < rown[i]) ? vb : 0.f;
            }
            acc[mt][nt][c0i]     = va;
            acc[mt][nt][c0i + 1] = vb;
        }
    }

    // per (row,frag): suffix over the 4 lanes of the group
    float sarr[4][4], ft[4][4];
    #pragma unroll
    for (int i = 0; i < 4; ++i) {
        const int mt = i >> 1, c0i = (i & 1) * 2;
        #pragma unroll
        for (int nt = 0; nt < 4; nt++) {
            float s = acc[mt][nt][c0i] + acc[mt][nt][c0i + 1];
            float u = __shfl_down_sync(FULL, s, 1);
            s += (tg < 3) ? u : 0.f;
            u = __shfl_down_sync(FULL, s, 2);
            s += (tg < 2) ? u : 0.f;
            sarr[i][nt] = s;
            ft[i][nt] = __shfl_sync(FULL, s, (threadIdx.x & 31) & ~3);
        }
    }

    if (tg == 0) {
        #pragma unroll
        for (int i = 0; i < 4; ++i)
            tot[cw * 128 + rown[i]] = ft[i][0] + ft[i][1] + ft[i][2] + ft[i][3];
    }
    __syncthreads();

    float2 yp[4];
    #pragma unroll
    for (int nt = 0; nt < 4; nt++)
        yp[nt] = *(const float2*)&yblk[cb + nt * 8 + 2 * tg];

    #pragma unroll
    for (int i = 0; i < 4; ++i) {
        const int r = rown[i];
        const float cy = ca_s[r];
        const float c0t = tot[r], c1t = tot[128 + r],
                    c2t = tot[256 + r], c3t = tot[384 + r];
        float base = cy;
        if (cw == 0)      base += c1t + c2t + c3t;
        else if (cw == 1) base += c2t + c3t;
        else if (cw == 2) base += c3t;
        pend[i] = cy + c0t + c1t + c2t + c3t;

        const int mt = i >> 1, c0i = (i & 1) * 2;
        float fsuf = 0.f;
        #pragma unroll
        for (int nt = 3; nt >= 0; --nt) {
            const float va = acc[mt][nt][c0i];
            const float vb = acc[mt][nt][c0i + 1];
            const float sa = base + fsuf + sarr[i][nt];
            const float wa = va * ex2f(nl2r[i] * sa);
            const float wb = vb * ex2f(nl2r[i] * (sa - va));
            Sacc[i] += wa + wb;
            Yacc[i] += yp[nt].x * wa + yp[nt].y * wb;
            fsuf += ft[i][nt];
        }
    }
}

// ---- Pass 2: main kernel ----
__global__ __launch_bounds__(NT, 1)
void ema_kernel(const float* __restrict__ y, float* __restrict__ out)
{
    extern __shared__ char smem[];
    __half* q_h  = (__half*)(smem + SM_Q);
    __half* k_h0 = (__half*)(smem + SM_K0);
    __half* k_h1 = (__half*)(smem + SM_K1);
    float*  y2   = (float*)(smem + SM_Y);
    float*  ca_s = (float*)(smem + SM_CA);
    float*  tot  = (float*)(smem + SM_TOT);

    const uint32_t q_sa = (uint32_t)__cvta_generic_to_shared(q_h);
    const uint32_t k_sa[2] = { (uint32_t)__cvta_generic_to_shared(k_h0),
                               (uint32_t)__cvta_generic_to_shared(k_h1) };
    const uint32_t y_sa = (uint32_t)__cvta_generic_to_shared(y2);

    const int tid  = threadIdx.x;
    const int lane = tid & 31;
    const int wid  = tid >> 5;
    const unsigned FULL = 0xffffffffu;

    const int g  = lane >> 2;
    const int tg = lane & 3;
    const int mrow0 = (wid >> 2) * 32;
    const int cw    = wid & 3;
    const int cb    = cw * 32;

    const int batch = blockIdx.x >> 2;
    const int pairp = blockIdx.x & 3;

    const __half* xbase = g_xn + (size_t)batch * TLEN * HID;
    const float*  ybase = y + batch * TLEN;

    int rown[4];
    #pragma unroll
    for (int i = 0; i < 4; ++i) rown[i] = mrow0 + 8 * i + g;

    for (int half = 0; half < 2; ++half) {
        const int qi = (half == 0) ? pairp : (7 - pairp);
        const int t0 = qi * 128;

        __syncthreads();

        // prologue: Q tile (2048 16B chunks) + y(qi) + carry init
        {
            const __half* qsrc = xbase + (size_t)t0 * HID;
            #pragma unroll
            for (int i = 0; i < 4; ++i) {
                const int c = tid + i * 512;
                const int r = c >> 4, j = c & 15;
                cp16(q_sa + r * 288 + j * 16, (const char*)qsrc + r * 256 + j * 16);
            }
            if (tid < 32) cp16(y_sa + tid * 16, ybase + qi * 128 + tid * 4);
            if (tid < 128) ca_s[tid] = 0.f;
        }
        float nl2r[4];
        #pragma unroll
        for (int i = 0; i < 4; ++i)
            nl2r[i] = g_nl2[batch * TLEN + t0 + rown[i]];
        cp_wait_all();
        __syncthreads();

        float Sacc[4] = {0.f, 0.f, 0.f, 0.f};
        float Yacc[4] = {0.f, 0.f, 0.f, 0.f};
        float pend[4];

        // it = 0: diagonal block (B = Q); prefetch K(qi-1), y(qi-1)
        if (qi > 0) {
            const __half* ksrc = xbase + (size_t)(qi - 1) * 128 * HID;
            #pragma unroll
            for (int i = 0; i < 4; ++i) {
                const int c = tid + i * 512;
                const int r = c >> 4, j = c & 15;
                cp16(k_sa[0] + r * 288 + j * 16, (const char*)ksrc + r * 256 + j * 16);
            }
            if (tid < 32)
                cp16(y_sa + 512 + tid * 16, ybase + (qi - 1) * 128 + tid * 4);
        }
        process_block<true>(q_h, q_h, y2, tot, ca_s, nl2r, rown,
                            Sacc, Yacc, pend, mrow0, cb, cw, g, tg);
        cp_wait_all();
        __syncthreads();
        if (cw == 0 && tg == 0) {
            #pragma unroll
            for (int i = 0; i < 4; ++i) ca_s[rown[i]] = pend[i];
        }

        for (int it = 1; it <= qi; ++it) {
            const int kb = qi - it;
            if (kb > 0) {
                const __half* ksrc = xbase + (size_t)(kb - 1) * 128 * HID;
                const uint32_t dst = k_sa[it & 1];
                #pragma unroll
                for (int i = 0; i < 4; ++i) {
                    const int c = tid + i * 512;
                    const int r = c >> 4, j = c & 15;
                    cp16(dst + r * 288 + j * 16, (const char*)ksrc + r * 256 + j * 16);
                }
                if (tid < 32)
                    cp16(y_sa + ((it + 1) & 1) * 512 + tid * 16,
                         ybase + (kb - 1) * 128 + tid * 4);
            }
            const __half* bsrc = (it & 1) ? k_h0 : k_h1;
            process_block<false>(q_h, bsrc, y2 + (it & 1) * 128, tot, ca_s,
                                 nl2r, rown, Sacc, Yacc, pend,
                                 mrow0, cb, cw, g, tg);
            cp_wait_all();
            __syncthreads();
            if (cw == 0 && tg == 0) {
                #pragma unroll
                for (int i = 0; i < 4; ++i) ca_s[rown[i]] = pend[i];
            }
        }

        // ---- epilogue ----
        #pragma unroll
        for (int i = 0; i < 4; ++i) {
            float s = Sacc[i], yv = Yacc[i];
            s  += __shfl_xor_sync(FULL, s, 1);  s  += __shfl_xor_sync(FULL, s, 2);
            yv += __shfl_xor_sync(FULL, yv, 1); yv += __shfl_xor_sync(FULL, yv, 2);
            if (tg == 0) {
                tot[cw * 128 + rown[i]]       = s;
                tot[512 + cw * 128 + rown[i]] = yv;
            }
        }
        __syncthreads();
        if (cw == 0) {
            #pragma unroll
            for (int i = 0; i < 4; ++i) {
                const int r = rown[i];
                float S = tot[r] + tot[128 + r] + tot[256 + r] + tot[384 + r];
                float Y = tot[512 + r] + tot[640 + r] + tot[768 + r] + tot[896 + r];
                float o = Y / (S + 1e-6f);
                o = fminf(fmaxf(o, 0.01f), 0.99f);
                out[batch * TLEN + t0 + r] = o;
            }
        }
    }
}

extern "C" void kernel_launch(void* const* d_in, const int* in_sizes, int n_in,
                              void* d_out, int out_size)
{
    const float* y    = (const float*)d_in[0];
    const int*   seq  = (const int*)  d_in[1];
    const float* embd = (const float*)d_in[2];
    const float* lw   = (const float*)d_in[3];
    const float* lb   = (const float*)d_in[4];
    float* out = (float*)d_out;

    cudaFuncSetAttribute(ema_kernel,
                         cudaFuncAttributeMaxDynamicSharedMemorySize, SMEM_BYTES);

    prep_kernel<<<BATCH * TLEN / 8, 256>>>(seq, embd, lw, lb);
    ema_kernel<<<BATCH * 4, NT, SMEM_BYTES>>>(y, out);
}

// round 10
// speedup vs baseline: 5.6096x; 1.1156x over previous
#include <cuda_runtime.h>
#include <cuda_fp16.h>
#include <cstdint>

#define BATCH 32
#define TLEN  1024
#define HID   128
#define LD_H  144              // halves per padded smem row (288 B)
#define NT    512
#define LOG2E 1.4426950408889634f

#define TILE_B (128 * LD_H * 2)        // 36864 B
#define SM_Q   0
#define SM_K0  TILE_B
#define SM_K1  (2 * TILE_B)
#define SM_Y   (3 * TILE_B)            // 2*128 floats
#define SM_TOT (SM_Y + 1024)           // 2*512 floats (double-buffered totals)
#define SMEM_BYTES (SM_TOT + 4096)

__device__ __half g_xn[(size_t)BATCH * TLEN * HID];  // fp16, k-permuted per 16-group
__device__ float  g_nl2[BATCH * TLEN];               // -lambda * log2(e)

__device__ __forceinline__ float ex2f(float x) {
    float y; asm("ex2.approx.ftz.f32 %0, %1;" : "=f"(y) : "f"(x)); return y;
}
__device__ __forceinline__ void mma_f16(float* c, uint32_t a0, uint32_t a1,
                                        uint32_t a2, uint32_t a3,
                                        uint32_t b0, uint32_t b1) {
    asm volatile(
        "mma.sync.aligned.m16n8k16.row.col.f32.f16.f16.f32 "
        "{%0,%1,%2,%3}, {%4,%5,%6,%7}, {%8,%9}, {%0,%1,%2,%3};"
        : "+f"(c[0]), "+f"(c[1]), "+f"(c[2]), "+f"(c[3])
        : "r"(a0), "r"(a1), "r"(a2), "r"(a3), "r"(b0), "r"(b1));
}
__device__ __forceinline__ void cp16(uint32_t dst, const void* src) {
    asm volatile("cp.async.ca.shared.global [%0], [%1], 16;" :: "r"(dst), "l"(src));
}
__device__ __forceinline__ void cp_wait_all() {
    asm volatile("cp.async.wait_all;" ::: "memory");
}

// ---- Pass 1: normalize each token once; store fp16 k-permuted ----
__global__ __launch_bounds__(256)
void prep_kernel(const int* __restrict__ seq,
                 const float* __restrict__ embd,
                 const float* __restrict__ lam_w,
                 const float* __restrict__ lam_b)
{
    const int lane = threadIdx.x & 31;
    const int wid  = threadIdx.x >> 5;
    const int row  = blockIdx.x * 8 + wid;
    const unsigned FULL = 0xffffffffu;

    const int e = seq[row];
    const float* w = embd + (size_t)e * HID;
    float v[4] = { w[lane], w[lane+32], w[lane+64], w[lane+96] };
    float ss = v[0]*v[0] + v[1]*v[1] + v[2]*v[2] + v[3]*v[3];
    float dl = v[0]*lam_w[lane] + v[1]*lam_w[lane+32]
             + v[2]*lam_w[lane+64] + v[3]*lam_w[lane+96];
    #pragma unroll
    for (int off = 16; off; off >>= 1) {
        ss += __shfl_xor_sync(FULL, ss, off);
        dl += __shfl_xor_sync(FULL, dl, off);
    }
    const float inv = rsqrtf(ss);
    __half* dst = g_xn + (size_t)row * HID;
    #pragma unroll
    for (int q = 0; q < 4; ++q) {
        const int c = lane + 32 * q;
        const int gk = c >> 4, u = (c >> 1) & 7, par = c & 1;
        const int slot = (u < 4) ? 2 * u : 2 * (u - 4) + 1;   // half2-unit permute
        dst[gk * 16 + slot * 2 + par] = __float2half_rn(v[q] * inv);
    }
    if (lane == 0) g_nl2[row] = -__expf(dl + lam_b[0]) * LOG2E;
}

// ---- one 128x128 key block: GEMM + fragment scan (single sync inside) ----
template<bool DIAG>
__device__ __forceinline__ void process_block(
    const __half* q_h, const __half* b_h, const float* yblk, float* totbuf,
    const float* nl2r, const int* rown, float* carry, float* Sacc, float* Yacc,
    int mrow0, int cb, int cw, int g, int tg)
{
    const unsigned FULL = 0xffffffffu;

    float acc[2][4][4];
    #pragma unroll
    for (int mt = 0; mt < 2; mt++)
        #pragma unroll
        for (int nt = 0; nt < 4; nt++)
            #pragma unroll
            for (int j = 0; j < 4; j++) acc[mt][nt][j] = 0.f;

    #pragma unroll
    for (int ks = 0; ks < 8; ++ks) {
        const int boff = ks * 16 + 4 * tg;
        uint2 a[2][2];
        #pragma unroll
        for (int mt = 0; mt < 2; ++mt) {
            const int r = mrow0 + mt * 16 + g;
            a[mt][0] = *(const uint2*)&q_h[r * LD_H + boff];
            a[mt][1] = *(const uint2*)&q_h[(r + 8) * LD_H + boff];
        }
        #pragma unroll
        for (int nt = 0; nt < 4; ++nt) {
            const int n = cb + nt * 8 + g;
            uint2 b = *(const uint2*)&b_h[n * LD_H + boff];
            mma_f16(acc[0][nt], a[0][0].x, a[0][1].x, a[0][0].y, a[0][1].y, b.x, b.y);
            mma_f16(acc[1][nt], a[1][0].x, a[1][1].x, a[1][0].y, a[1][1].y, b.x, b.y);
        }
    }

    // mask + (x+1)/2
    const int col0 = cb + 2 * tg;
    #pragma unroll
    for (int i = 0; i < 4; ++i) {
        const int mt = i >> 1, c0i = (i & 1) * 2;
        #pragma unroll
        for (int nt = 0; nt < 4; nt++) {
            float va = fmaf(acc[mt][nt][c0i],     0.5f, 0.5f);
            float vb = fmaf(acc[mt][nt][c0i + 1], 0.5f, 0.5f);
            if (DIAG) {
                va = (col0 + nt * 8     < rown[i]) ? va : 0.f;
                vb = (col0 + nt * 8 + 1 < rown[i]) ? vb : 0.f;
            }
            acc[mt][nt][c0i]     = va;
            acc[mt][nt][c0i + 1] = vb;
        }
    }

    // per (row,frag): suffix over the 4 lanes of the group
    float sarr[4][4], ft[4][4];
    #pragma unroll
    for (int i = 0; i < 4; ++i) {
        const int mt = i >> 1, c0i = (i & 1) * 2;
        #pragma unroll
        for (int nt = 0; nt < 4; nt++) {
            float s = acc[mt][nt][c0i] + acc[mt][nt][c0i + 1];
            float u = __shfl_down_sync(FULL, s, 1);
            s += (tg < 3) ? u : 0.f;
            u = __shfl_down_sync(FULL, s, 2);
            s += (tg < 2) ? u : 0.f;
            sarr[i][nt] = s;
            ft[i][nt] = __shfl_sync(FULL, s, (threadIdx.x & 31) & ~3);
        }
    }

    if (tg == 0) {
        #pragma unroll
        for (int i = 0; i < 4; ++i)
            totbuf[cw * 128 + rown[i]] = ft[i][0] + ft[i][1] + ft[i][2] + ft[i][3];
    }
    cp_wait_all();          // prefetched K/y for next block complete (this thread)
    __syncthreads();        // totals visible + smem copies visible, ONE barrier

    float2 yp[4];
    #pragma unroll
    for (int nt = 0; nt < 4; nt++)
        yp[nt] = *(const float2*)&yblk[cb + nt * 8 + 2 * tg];

    #pragma unroll
    for (int i = 0; i < 4; ++i) {
        const int r = rown[i];
        const float c0t = totbuf[r],       c1t = totbuf[128 + r],
                    c2t = totbuf[256 + r], c3t = totbuf[384 + r];
        float base = carry[i];
        if (cw == 0)      base += c1t + c2t + c3t;
        else if (cw == 1) base += c2t + c3t;
        else if (cw == 2) base += c3t;
        carry[i] += c0t + c1t + c2t + c3t;   // register carry, every lane

        const int mt = i >> 1, c0i = (i & 1) * 2;
        float fsuf = 0.f;
        #pragma unroll
        for (int nt = 3; nt >= 0; --nt) {
            const float va = acc[mt][nt][c0i];
            const float vb = acc[mt][nt][c0i + 1];
            const float sa = base + fsuf + sarr[i][nt];
            const float wa = va * ex2f(nl2r[i] * sa);
            const float wb = vb * ex2f(nl2r[i] * (sa - va));
            Sacc[i] += wa + wb;
            Yacc[i] += yp[nt].x * wa + yp[nt].y * wb;
            fsuf += ft[i][nt];
        }
    }
}

// ---- Pass 2: main kernel, one query tile per CTA, LPT order ----
__global__ __launch_bounds__(NT, 1)
void ema_kernel(const float* __restrict__ y, float* __restrict__ out)
{
    extern __shared__ char smem[];
    __half* q_h  = (__half*)(smem + SM_Q);
    __half* k_h0 = (__half*)(smem + SM_K0);
    __half* k_h1 = (__half*)(smem + SM_K1);
    float*  y2   = (float*)(smem + SM_Y);
    float*  tot  = (float*)(smem + SM_TOT);

    const uint32_t q_sa = (uint32_t)__cvta_generic_to_shared(q_h);
    const uint32_t k_sa[2] = { (uint32_t)__cvta_generic_to_shared(k_h0),
                               (uint32_t)__cvta_generic_to_shared(k_h1) };
    const uint32_t y_sa = (uint32_t)__cvta_generic_to_shared(y2);

    const int tid  = threadIdx.x;
    const int lane = tid & 31;
    const int wid  = tid >> 5;
    const unsigned FULL = 0xffffffffu;

    const int g  = lane >> 2;
    const int tg = lane & 3;
    const int mrow0 = (wid >> 2) * 32;
    const int cw    = wid & 3;
    const int cb    = cw * 32;

    // LPT: heavy tiles (qi=7) first
    const int batch = blockIdx.x & 31;
    const int qi    = 7 - (blockIdx.x >> 5);
    const int t0    = qi * 128;

    const __half* xbase = g_xn + (size_t)batch * TLEN * HID;
    const float*  ybase = y + batch * TLEN;

    int rown[4];
    #pragma unroll
    for (int i = 0; i < 4; ++i) rown[i] = mrow0 + 8 * i + g;

    // prologue: Q tile + y(qi)
    {
        const __half* qsrc = xbase + (size_t)t0 * HID;
        #pragma unroll
        for (int i = 0; i < 4; ++i) {
            const int c = tid + i * 512;
            const int r = c >> 4, j = c & 15;
            cp16(q_sa + r * 288 + j * 16, (const char*)qsrc + r * 256 + j * 16);
        }
        if (tid < 32) cp16(y_sa + tid * 16, ybase + qi * 128 + tid * 4);
    }
    float nl2r[4];
    #pragma unroll
    for (int i = 0; i < 4; ++i)
        nl2r[i] = g_nl2[batch * TLEN + t0 + rown[i]];
    cp_wait_all();
    __syncthreads();

    float carry[4] = {0.f, 0.f, 0.f, 0.f};
    float Sacc[4]  = {0.f, 0.f, 0.f, 0.f};
    float Yacc[4]  = {0.f, 0.f, 0.f, 0.f};

    for (int it = 0; it <= qi; ++it) {
        const int kb = qi - it;

        // prefetch K(kb-1) -> kbuf[it&1], y(kb-1) -> ybuf[(it+1)&1]
        if (kb > 0) {
            const __half* ksrc = xbase + (size_t)(kb - 1) * 128 * HID;
            const uint32_t dst = k_sa[it & 1];
            #pragma unroll
            for (int i = 0; i < 4; ++i) {
                const int c = tid + i * 512;
                const int r = c >> 4, j = c & 15;
                cp16(dst + r * 288 + j * 16, (const char*)ksrc + r * 256 + j * 16);
            }
            if (tid < 32)
                cp16(y_sa + ((it + 1) & 1) * 512 + tid * 16,
                     ybase + (kb - 1) * 128 + tid * 4);
        }

        float* totbuf = tot + (it & 1) * 512;
        const float* yblk = y2 + (it & 1) * 128;
        if (it == 0) {
            process_block<true>(q_h, q_h, yblk, totbuf, nl2r, rown,
                                carry, Sacc, Yacc, mrow0, cb, cw, g, tg);
        } else {
            const __half* bsrc = (it & 1) ? k_h0 : k_h1;   // written at it-1
            process_block<false>(q_h, bsrc, yblk, totbuf, nl2r, rown,
                                 carry, Sacc, Yacc, mrow0, cb, cw, g, tg);
        }
    }

    // ---- epilogue ----
    __syncthreads();   // all weight loops done reading tot
    #pragma unroll
    for (int i = 0; i < 4; ++i) {
        float s = Sacc[i], yv = Yacc[i];
        s  += __shfl_xor_sync(FULL, s, 1);  s  += __shfl_xor_sync(FULL, s, 2);
        yv += __shfl_xor_sync(FULL, yv, 1); yv += __shfl_xor_sync(FULL, yv, 2);
        if (tg == 0) {
            tot[cw * 128 + rown[i]]       = s;
            tot[512 + cw * 128 + rown[i]] = yv;
        }
    }
    __syncthreads();
    if (cw == 0) {
        #pragma unroll
        for (int i = 0; i < 4; ++i) {
            const int r = rown[i];
            float S = tot[r] + tot[128 + r] + tot[256 + r] + tot[384 + r];
            float Y = tot[512 + r] + tot[640 + r] + tot[768 + r] + tot[896 + r];
            float o = Y / (S + 1e-6f);
            o = fminf(fmaxf(o, 0.01f), 0.99f);
            out[batch * TLEN + t0 + r] = o;
        }
    }
}

extern "C" void kernel_launch(void* const* d_in, const int* in_sizes, int n_in,
                              void* d_out, int out_size)
{
    const float* y    = (const float*)d_in[0];
    const int*   seq  = (const int*)  d_in[1];
    const float* embd = (const float*)d_in[2];
    const float* lw   = (const float*)d_in[3];
    const float* lb   = (const float*)d_in[4];
    float* out = (float*)d_out;

    cudaFuncSetAttribute(ema_kernel,
                         cudaFuncAttributeMaxDynamicSharedMemorySize, SMEM_BYTES);

    prep_kernel<<<BATCH * TLEN / 8, 256>>>(seq, embd, lw, lb);
    ema_kernel<<<BATCH * 8, NT, SMEM_BYTES>>>(y, out);
}